// round 6
// baseline (speedup 1.0000x reference)
#include <cuda_runtime.h>
#include <math.h>

#define HW   4096
#define NB   8
#define NFC  768
#define NRC  8
#define NP   8

typedef unsigned long long ull;

// ---------------- scratch ----------------
__device__ float g_cpre[NB*NRC*HW];
__device__ float g_car [NB*NRC*HW];
__device__ float g_cm  [NB*HW];
__device__ float g_dn  [NB*HW];
__device__ float g_hp  [NB*HW];
__device__ float g_cs  [NB*HW];
__device__ float g_g0  [NB*HW];
__device__ float g_er  [NB*HW];
__device__ float g_s0  [NB*HW];
__device__ float g_sf  [NB*HW];
__device__ float g_st  [NB*8];
__device__ float g_kern[NP*81];

// ---------------- helpers ----------------
__device__ __forceinline__ ull pack2(float lo, float hi){ ull r; asm("mov.b64 %0,{%1,%2};":"=l"(r):"f"(lo),"f"(hi)); return r; }
__device__ __forceinline__ ull fma2(ull a, ull b, ull c){ ull d; asm("fma.rn.f32x2 %0,%1,%2,%3;":"=l"(d):"l"(a),"l"(b),"l"(c)); return d; }
__device__ __forceinline__ ull add2(ull a, ull b){ ull d; asm("add.rn.f32x2 %0,%1,%2;":"=l"(d):"l"(a),"l"(b)); return d; }
__device__ __forceinline__ void unpack2(ull v, float&lo, float&hi){ asm("mov.b64 {%0,%1},%2;":"=f"(lo),"=f"(hi):"l"(v)); }
__device__ __forceinline__ float geluf(float x){ return 0.5f*x*(1.0f+erff(x*0.70710678118654752f)); }
__device__ __forceinline__ float sigm(float x){ return 1.0f/(1.0f+expf(-x)); }

// ---------------- K0: build prototype kernel bank once ----------------
__global__ __launch_bounds__(256) void k0_bank(const float* __restrict__ pdelta){
    __shared__ float ridge[NP*81];
    int tid = threadIdx.x;
    for (int i = tid; i < NP*81; i += 256){
        int p = i/81, idx = i%81, ky = idx/9, kx = idx%9;
        float yy = -1.0f + 0.25f*ky, xx = -1.0f + 0.25f*kx;
        double ang = 6.283185307179586 * p / 8.0;
        float ca = (float)cos(ang), sa = (float)sin(ang);
        const float Ls[3] = {0.45f, 0.75f, 1.05f};
        const float Wv[3] = {0.14f, 0.2f, 0.28f};
        float L = Ls[p%3], W = Wv[(p/3)%3];
        float xr = xx*ca + yy*sa;
        float yr = -xx*sa + yy*ca;
        float tp = powf(1.0f - fminf(fabsf(xr)/L, 1.0f), 1.5f);
        float yrw = yr / W;
        float core = expf(-0.5f*((xr/L)*(xr/L) + yrw*yrw));
        ridge[i] = tp * core * fmaxf(1.0f - yrw*yrw, 0.0f);
    }
    __syncthreads();
    int w = tid >> 5, lane = tid & 31;  // warp w handles prototype w
    const float* rp = ridge + w*81;
    float s = 0.f;
    for (int j = lane; j < 81; j += 32) s += rp[j];
    #pragma unroll
    for (int o = 16; o > 0; o >>= 1) s += __shfl_xor_sync(0xffffffffu, s, o);
    float mean = s*(1.0f/81.0f);
    float a = 0.f;
    for (int j = lane; j < 81; j += 32) a += fabsf(rp[j]-mean);
    #pragma unroll
    for (int o = 16; o > 0; o >>= 1) a += __shfl_xor_sync(0xffffffffu, a, o);
    float den = fmaxf(a, 1e-6f);
    for (int j = lane; j < 81; j += 32)
        g_kern[w*81+j] = (rp[j]-mean)/den + 0.05f*pdelta[w*81+j];
}

// ---------------- K1: 768 -> 8 1x1 conv + gelu; 8-way K-split ----------------
__global__ __launch_bounds__(256) void k1_gemm(const float* __restrict__ fm,
                                               const float* __restrict__ w,
                                               const float* __restrict__ bv){
    __shared__ ull ws[NFC*NRC];                       // (w,w) packed, c-major
    for (int i = threadIdx.x; i < NFC*NRC; i += 256){
        int c = i >> 3, r = i & 7;
        float v = w[r*NFC + c];
        ws[i] = pack2(v, v);
    }
    __syncthreads();
    int t = blockIdx.x*256 + threadIdx.x;             // 0..131071
    int pair = t >> 3, s = t & 7;                     // K-chunk index
    int b = pair >> 11; int p = (pair & 2047) << 1;
    const float* x = fm + (size_t)b*NFC*HW + (size_t)(s*96)*HW + p;
    const ull* wsp = ws + s*96*8;
    ull acc[NRC];
    #pragma unroll
    for (int r = 0; r < NRC; r++) acc[r] = 0ull;
    #pragma unroll 8
    for (int c = 0; c < 96; c++){
        ull xv = *(const ull*)(x + (size_t)c*HW);
        const ull* wc = wsp + c*8;
        #pragma unroll
        for (int r = 0; r < NRC; r++) acc[r] = fma2(wc[r], xv, acc[r]);
    }
    // log2(8) tree: lane s ends owning channel s, full K-sum
    ull tr[8];
    #pragma unroll
    for (int r = 0; r < 8; r++) tr[r] = add2(acc[r], __shfl_xor_sync(0xffffffffu, acc[r], 4));
    ull a4[4];
    #pragma unroll
    for (int j = 0; j < 4; j++) a4[j] = (s & 4) ? tr[j+4] : tr[j];
    #pragma unroll
    for (int j = 0; j < 4; j++) a4[j] = add2(a4[j], __shfl_xor_sync(0xffffffffu, a4[j], 2));
    ull a2[2];
    a2[0] = (s & 2) ? a4[2] : a4[0];
    a2[1] = (s & 2) ? a4[3] : a4[1];
    #pragma unroll
    for (int j = 0; j < 2; j++) a2[j] = add2(a2[j], __shfl_xor_sync(0xffffffffu, a2[j], 1));
    ull a1 = (s & 1) ? a2[1] : a2[0];
    float lo, hi; unpack2(a1, lo, hi);
    float bb = bv[s]; lo += bb; hi += bb;
    float2 v; v.x = geluf(lo); v.y = geluf(hi);
    *(float2*)(g_cpre + (size_t)b*NRC*HW + (size_t)s*HW + p) = v;
}

// ---------------- K2: 3x3 conv 8->8 + gelu + channel stats ----------------
__global__ __launch_bounds__(256) void k2_conv3(const float* __restrict__ w,
                                                const float* __restrict__ bv){
    __shared__ float ws[NRC*NRC*9];
    __shared__ float bs[NRC];
    for (int i = threadIdx.x; i < NRC*NRC*9; i += 256) ws[i] = w[i];
    if (threadIdx.x < NRC) bs[threadIdx.x] = bv[threadIdx.x];
    __syncthreads();
    int t = blockIdx.x*256 + threadIdx.x;
    int b = t >> 12, pix = t & 4095, y = pix >> 6, x = pix & 63;
    float acc[NRC];
    #pragma unroll
    for (int r = 0; r < NRC; r++) acc[r] = bs[r];
    const float* in = g_cpre + (size_t)b*NRC*HW;
    #pragma unroll
    for (int ic = 0; ic < NRC; ic++){
        #pragma unroll
        for (int dy = -1; dy <= 1; dy++){
            int yy = y + dy; if (yy < 0 || yy > 63) continue;
            #pragma unroll
            for (int dx = -1; dx <= 1; dx++){
                int xx = x + dx; if (xx < 0 || xx > 63) continue;
                float v = in[ic*HW + yy*64 + xx];
                int tap = ic*9 + (dy+1)*3 + (dx+1);
                #pragma unroll
                for (int oc = 0; oc < NRC; oc++)
                    acc[oc] = fmaf(ws[oc*72 + tap], v, acc[oc]);
            }
        }
    }
    float m = 0.f, a = 0.f;
    float* oc_out = g_car + (size_t)b*NRC*HW + pix;
    #pragma unroll
    for (int r = 0; r < NRC; r++){
        float c = geluf(acc[r]);
        oc_out[r*HW] = c;
        m += c; a += fabsf(c);
    }
    g_cm[t] = m * 0.125f;
    g_dn[t] = a * 0.125f;
}

// ---------------- K3+K4 fused ----------------
__global__ __launch_bounds__(1024) void k3_hp_stats(){
    int b = blockIdx.x;
    __shared__ float cms[64*64];
    __shared__ float hps[66*68];
    __shared__ float red[5][32];
    int tid = threadIdx.x;
    const float* cm = g_cm + b*HW;
    float4 c4 = ((const float4*)cm)[tid];
    ((float4*)cms)[tid] = c4;
    if (tid < 66){
        hps[tid] = 0.f; hps[65*68 + tid] = 0.f;
        hps[tid*68] = 0.f; hps[tid*68 + 65] = 0.f;
    }
    __syncthreads();
    int y = tid >> 4, x0 = (tid & 15) << 2;
    float4 hp4;
    float* hp4p = &hp4.x;
    #pragma unroll
    for (int k = 0; k < 4; k++){
        int x = x0 + k;
        float s = 0.f;
        #pragma unroll
        for (int dy = -1; dy <= 1; dy++){
            int yy = y + dy; if (yy < 0 || yy > 63) continue;
            #pragma unroll
            for (int dx = -1; dx <= 1; dx++){
                int xx = x + dx; if (xx < 0 || xx > 63) continue;
                s += cms[yy*64 + xx];
            }
        }
        float h = cms[y*64 + x] - s*(1.0f/9.0f);
        hp4p[k] = h;
        hps[(y+1)*68 + (x+1)] = h;
    }
    ((float4*)(g_hp + b*HW))[tid] = hp4;
    __syncthreads();
    float cmn = 1e30f, cmx = -1e30f;
    float4 cs4;
    float* cs4p = &cs4.x;
    #pragma unroll
    for (int k = 0; k < 4; k++){
        int x = x0 + k;
        float s = 0.f;
        #pragma unroll
        for (int dy = 0; dy < 3; dy++)
            #pragma unroll
            for (int dx = 0; dx < 3; dx++)
                s += fabsf(hps[(y+dy)*68 + (x+dx)]);
        float cs = s*(1.0f/9.0f);
        cs4p[k] = cs;
        cmn = fminf(cmn, cs); cmx = fmaxf(cmx, cs);
    }
    ((float4*)(g_cs + b*HW))[tid] = cs4;
    float4 d4 = ((const float4*)(g_dn + b*HW))[tid];
    float dmn = fminf(fminf(d4.x, d4.y), fminf(d4.z, d4.w));
    float dmx = fmaxf(fmaxf(d4.x, d4.y), fmaxf(d4.z, d4.w));
    float ds  = (d4.x + d4.y) + (d4.z + d4.w);
    #pragma unroll
    for (int o = 16; o > 0; o >>= 1){
        cmn = fminf(cmn, __shfl_xor_sync(0xffffffffu, cmn, o));
        cmx = fmaxf(cmx, __shfl_xor_sync(0xffffffffu, cmx, o));
        dmn = fminf(dmn, __shfl_xor_sync(0xffffffffu, dmn, o));
        dmx = fmaxf(dmx, __shfl_xor_sync(0xffffffffu, dmx, o));
        ds += __shfl_xor_sync(0xffffffffu, ds, o);
    }
    int wid = tid >> 5, lane = tid & 31;
    if (lane == 0){ red[0][wid]=cmn; red[1][wid]=cmx; red[2][wid]=dmn; red[3][wid]=dmx; red[4][wid]=ds; }
    __syncthreads();
    if (tid < 32){
        cmn = red[0][tid]; cmx = red[1][tid]; dmn = red[2][tid]; dmx = red[3][tid]; ds = red[4][tid];
        #pragma unroll
        for (int o = 16; o > 0; o >>= 1){
            cmn = fminf(cmn, __shfl_xor_sync(0xffffffffu, cmn, o));
            cmx = fmaxf(cmx, __shfl_xor_sync(0xffffffffu, cmx, o));
            dmn = fminf(dmn, __shfl_xor_sync(0xffffffffu, dmn, o));
            dmx = fmaxf(dmx, __shfl_xor_sync(0xffffffffu, dmx, o));
            ds += __shfl_xor_sync(0xffffffffu, ds, o);
        }
        if (tid == 0){
            float* st = g_st + b*8;
            st[0]=cmn; st[1]=cmx; st[2]=dmn; st[3]=dmx; st[4]=ds*(1.0f/4096.0f);
        }
    }
}

// ---------------- K5: top2-softmax responses + ev/gate0 + erosion ----------------
__global__ __launch_bounds__(256) void k5_main(const float* __restrict__ theta,
                                               const float* __restrict__ length,
                                               const float* __restrict__ width,
                                               const float* __restrict__ plog){
    __shared__ float hps[24*24];
    __shared__ float kern[NP*81];
    __shared__ float m0s[20*20];
    int blk = blockIdx.x; int b = blk >> 4; int tile = blk & 15;
    int ty0 = (tile >> 2) << 4, tx0 = (tile & 3) << 4;

    const float* hp = g_hp + b*HW;
    for (int i = threadIdx.x; i < 576; i += 256){
        int ly = i/24, lx = i%24;
        int gy = ty0-4+ly, gx = tx0-4+lx;
        hps[i] = (gy>=0 && gy<64 && gx>=0 && gx<64) ? hp[gy*64+gx] : 0.f;
    }
    for (int i = threadIdx.x; i < NP*81; i += 256) kern[i] = g_kern[i];

    const float* st = g_st + b*8;
    float csmn = st[0], csmx = st[1], dmn = st[2], dmx = st[3];
    float m = fmaxf(st[4], 1e-6f);
    float csden = fmaxf(csmx - csmn, 1e-6f);
    float ddmn = dmn/m, ddmx = dmx/m;
    float dsden = fmaxf(ddmx - ddmn, 1e-6f);
    const float* csb = g_cs + b*HW; const float* dnb = g_dn + b*HW;
    for (int i = threadIdx.x; i < 400; i += 256){
        int ly = i/20, lx = i%20;
        int gy = ty0-2+ly, gx = tx0-2+lx;
        float v = 1.0f;
        if (gy>=0 && gy<64 && gx>=0 && gx<64){
            int gi = gy*64+gx;
            float csn = (csb[gi]-csmn)/csden;
            float dsn = (dnb[gi]/m - ddmn)/dsden;
            float ev = 0.65f*csn + 0.35f*dsn;
            v = (ev >= 0.2f) ? 1.0f : 0.0f;
        }
        m0s[i] = v;
    }
    __syncthreads();

    int ty = threadIdx.x >> 4, tx = threadIdx.x & 15;
    int gy = ty0 + ty, gx = tx0 + tx;
    int gi = gy*64 + gx; int t = b*HW + gi;
    {
        float csn = (csb[gi]-csmn)/csden;
        float dsn = (dnb[gi]/m - ddmn)/dsden;
        float ev = 0.65f*csn + 0.35f*dsn;
        g_g0[t] = sigm((ev - 0.2f)/0.08f);
    }
    {
        float e = 1.0f;
        #pragma unroll
        for (int dy = 0; dy < 5; dy++)
            #pragma unroll
            for (int dx = 0; dx < 5; dx++) e = fminf(e, m0s[(ty+dy)*20 + (tx+dx)]);
        g_er[t] = e;
    }
    float bias[NP];
    float ta = tanhf(theta[t]) * 3.14159265358979323846f;
    float lv = sigm(length[t])*0.85f + 0.25f;
    float wv = sigm(width[t])*0.22f + 0.08f;
    const float Ls[3] = {0.45f, 0.75f, 1.05f};
    const float Wv[3] = {0.14f, 0.2f, 0.28f};
    #pragma unroll
    for (int p = 0; p < NP; p++){
        float ori = (float)(6.283185307179586 * p / 8.0);
        float la = Ls[p%3], wa = Wv[(p/3)%3];
        float dl = lv - la, dw = wv - wa;
        bias[p] = plog[(size_t)b*NP*HW + p*HW + gi]
                + 1.25f*cosf(ta - ori)
                - dl*dl/0.08f
                - dw*dw/0.01f;
    }
    int i1 = 0; float m1 = bias[0];
    #pragma unroll
    for (int p = 1; p < NP; p++) if (bias[p] > m1){ m1 = bias[p]; i1 = p; }
    int i2 = (i1 == 0) ? 1 : 0; float m2 = -1e30f;
    #pragma unroll
    for (int p = 0; p < NP; p++) if (p != i1 && bias[p] > m2){ m2 = bias[p]; i2 = p; }
    float e2 = expf(m2 - m1);
    float inv = 1.0f/(1.0f + e2);
    float pw1 = inv, pw2 = e2*inv;

    const float* k1p = kern + i1*81;
    const float* k2p = kern + i2*81;
    float r1 = 0.f, r2v = 0.f;
    #pragma unroll
    for (int ky = 0; ky < 9; ky++){
        #pragma unroll
        for (int kx = 0; kx < 9; kx++){
            float v = hps[(ty+ky)*24 + (tx+kx)];
            r1  = fmaf(k1p[ky*9+kx], v, r1);
            r2v = fmaf(k2p[ky*9+kx], v, r2v);
        }
    }
    g_s0[t] = pw1*r1 + pw2*r2v;
}

// ---------------- K7: dilate/open combine + stroke gate + final ss ----------------
__global__ __launch_bounds__(256) void k7_comb(const float* __restrict__ obj,
                                               const float* __restrict__ alpha,
                                               const float* __restrict__ curv){
    int t = blockIdx.x*256 + threadIdx.x;
    int b = t >> 12, pix = t & 4095, y = pix >> 6, x = pix & 63;
    const float* er = g_er + b*HW;
    const float* g0 = g_g0 + b*HW;
    const float* s0 = g_s0 + b*HW;
    float mask = 0.f;
    {
        int y0 = max(y-4,0), y1 = min(y+4,63), x0 = max(x-4,0), x1 = min(x+4,63);
        for (int yy = y0; yy <= y1; yy++)
            for (int xx = x0; xx <= x1; xx++) mask = fmaxf(mask, er[yy*64+xx]);
    }
    float gate = 0.f;
    {
        int y0 = max(y-2,0), y1 = min(y+2,63), x0 = max(x-2,0), x1 = min(x+2,63);
        for (int yy = y0; yy <= y1; yy++)
            for (int xx = x0; xx <= x1; xx++) gate = fmaxf(gate, g0[yy*64+xx]);
    }
    float blob = 0.f, ssum = 0.f;
    const float* ob = obj + b*HW;
    {
        int y0 = max(y-1,0), y1 = min(y+1,63), x0 = max(x-1,0), x1 = min(x+1,63);
        for (int yy = y0; yy <= y1; yy++)
            for (int xx = x0; xx <= x1; xx++){
                blob += sigm(ob[yy*64+xx]);
                ssum += s0[yy*64+xx];
            }
    }
    blob *= (1.0f/9.0f);
    float ss1 = s0[pix] - ssum*(1.0f/9.0f);
    float gatef = gate * mask;
    float dmean = fmaxf(g_st[b*8+4], 1e-6f);
    float dens = g_dn[t] / dmean;
    float sg = sigm(alpha[t]) * (blob * gatef) * (0.7f + 0.3f*fminf(fmaxf(dens, 0.f), 2.f));
    g_sf[t] = sg * ss1 * (1.0f + 0.15f*tanhf(curv[t]));
}

// ---------------- K8: feats -> 8 (gelu) -> 768 expansion; 4-way output split ----------------
__global__ __launch_bounds__(256) void k8_out(const float* __restrict__ theta,
                                              const float* __restrict__ curv,
                                              const float* __restrict__ w1,
                                              const float* __restrict__ b1,
                                              const float* __restrict__ w2,
                                              const float* __restrict__ b2,
                                              float* __restrict__ out){
    extern __shared__ ull sh[];
    ull*   w2p = sh;                                  // 6144 packed pairs
    float* b2s = (float*)(sh + NFC*NRC);              // 768
    ull*   w1p = (ull*)(b2s + NFC);                   // 96
    float* b1s = (float*)(w1p + 96);                  // 8
    for (int i = threadIdx.x; i < NFC*NRC; i += 256){ float v = w2[i]; w2p[i] = pack2(v, v); }
    for (int i = threadIdx.x; i < NFC; i += 256) b2s[i] = b2[i];
    for (int i = threadIdx.x; i < 96; i += 256){ float v = w1[i]; w1p[i] = pack2(v, v); }
    if (threadIdx.x < 8) b1s[threadIdx.x] = b1[threadIdx.x];
    __syncthreads();

    int t = blockIdx.x*256 + threadIdx.x;             // 0..65535
    int pair = t >> 2, q = t & 3;
    int b = pair >> 11; int p = (pair & 2047) << 1;
    int base = b*HW + p;
    float2 ss = *(const float2*)(g_sf + base);
    float2 th = *(const float2*)(theta + base);
    float2 cv = *(const float2*)(curv + base);
    ull f[12];
    const float* car = g_car + (size_t)b*NRC*HW + p;
    #pragma unroll
    for (int r = 0; r < NRC; r++){
        float2 c = *(const float2*)(car + (size_t)r*HW);
        f[r] = pack2(c.x*ss.x, c.y*ss.y);
    }
    f[8] = pack2(ss.x, ss.y);
    const float PIF = 3.14159265358979323846f;
    float a0 = tanhf(th.x)*PIF, a1 = tanhf(th.y)*PIF;
    f[9]  = pack2(cosf(a0)*ss.x, cosf(a1)*ss.y);
    f[10] = pack2(sinf(a0)*ss.x, sinf(a1)*ss.y);
    f[11] = pack2(tanhf(cv.x)*ss.x, tanhf(cv.y)*ss.y);

    ull h[NRC];
    #pragma unroll
    for (int r = 0; r < NRC; r++){
        ull acc = pack2(b1s[r], b1s[r]);
        #pragma unroll
        for (int j = 0; j < 12; j++) acc = fma2(w1p[r*12+j], f[j], acc);
        float lo, hi; unpack2(acc, lo, hi);
        h[r] = pack2(geluf(lo), geluf(hi));
    }
    float* o = out + (size_t)b*NFC*HW + p;
    int fc0 = q * 192;
    #pragma unroll 4
    for (int j = 0; j < 192; j++){
        int fc = fc0 + j;
        float bb = b2s[fc];
        ull acc = pack2(bb, bb);
        const ull* wr = w2p + fc*8;
        #pragma unroll
        for (int r = 0; r < NRC; r++) acc = fma2(wr[r], h[r], acc);
        float2 v; unpack2(acc, v.x, v.y);
        *(float2*)(o + (size_t)fc*HW) = v;
    }
}

// ---------------- host ----------------
extern "C" void kernel_launch(void* const* d_in, const int* in_sizes, int n_in,
                              void* d_out, int out_size){
    const float* fm    = (const float*)d_in[0];
    const float* theta = (const float*)d_in[1];
    const float* len   = (const float*)d_in[2];
    const float* wid   = (const float*)d_in[3];
    const float* curv  = (const float*)d_in[4];
    const float* alpha = (const float*)d_in[5];
    const float* obj   = (const float*)d_in[6];
    const float* plog  = (const float*)d_in[7];
    const float* fp1w  = (const float*)d_in[8];
    const float* fp1b  = (const float*)d_in[9];
    const float* fp2w  = (const float*)d_in[10];
    const float* fp2b  = (const float*)d_in[11];
    const float* pm1w  = (const float*)d_in[12];
    const float* pm1b  = (const float*)d_in[13];
    const float* pm2w  = (const float*)d_in[14];
    const float* pm2b  = (const float*)d_in[15];
    const float* pdel  = (const float*)d_in[16];

    cudaFuncSetAttribute(k8_out, cudaFuncAttributeMaxDynamicSharedMemorySize, 53056);

    k0_bank<<<1,256>>>(pdel);
    k1_gemm<<<512,256>>>(fm, fp1w, fp1b);
    k2_conv3<<<128,256>>>(fp2w, fp2b);
    k3_hp_stats<<<8,1024>>>();
    k5_main<<<128,256>>>(theta, len, wid, plog);
    k7_comb<<<128,256>>>(obj, alpha, curv);
    k8_out<<<256,256,53056>>>(theta, curv, pm1w, pm1b, pm2w, pm2b, (float*)d_out);
}

// round 8
// speedup vs baseline: 3.0041x; 3.0041x over previous
#include <cuda_runtime.h>
#include <math.h>

#define HW   4096
#define NB   8
#define NFC  768
#define NRC  8
#define NP   8

typedef unsigned long long ull;

// ---------------- scratch ----------------
__device__ float g_cpre[NB*NRC*HW];
__device__ float g_car [NB*NRC*HW];
__device__ float g_cm  [NB*HW];
__device__ float g_dn  [NB*HW];
__device__ float g_hp  [NB*HW];
__device__ float g_cs  [NB*HW];
__device__ float g_g0  [NB*HW];
__device__ float g_er  [NB*HW];
__device__ float g_s0  [NB*HW];
__device__ float g_sf  [NB*HW];
__device__ float g_st  [NB*8];
__device__ float g_kern[NP*81];

// ---------------- helpers ----------------
__device__ __forceinline__ ull pack2(float lo, float hi){ ull r; asm("mov.b64 %0,{%1,%2};":"=l"(r):"f"(lo),"f"(hi)); return r; }
__device__ __forceinline__ ull fma2(ull a, ull b, ull c){ ull d; asm("fma.rn.f32x2 %0,%1,%2,%3;":"=l"(d):"l"(a),"l"(b),"l"(c)); return d; }
__device__ __forceinline__ ull add2(ull a, ull b){ ull d; asm("add.rn.f32x2 %0,%1,%2;":"=l"(d):"l"(a),"l"(b)); return d; }
__device__ __forceinline__ void unpack2(ull v, float&lo, float&hi){ asm("mov.b64 {%0,%1},%2;":"=f"(lo),"=f"(hi):"l"(v)); }
__device__ __forceinline__ float geluf(float x){ return 0.5f*x*(1.0f+erff(x*0.70710678118654752f)); }
__device__ __forceinline__ float sigm(float x){ return 1.0f/(1.0f+expf(-x)); }

// ---------------- K0: build prototype kernel bank once ----------------
__global__ __launch_bounds__(256) void k0_bank(const float* __restrict__ pdelta){
    __shared__ float ridge[NP*81];
    int tid = threadIdx.x;
    for (int i = tid; i < NP*81; i += 256){
        int p = i/81, idx = i%81, ky = idx/9, kx = idx%9;
        float yy = -1.0f + 0.25f*ky, xx = -1.0f + 0.25f*kx;
        double ang = 6.283185307179586 * p / 8.0;
        float ca = (float)cos(ang), sa = (float)sin(ang);
        const float Ls[3] = {0.45f, 0.75f, 1.05f};
        const float Wv[3] = {0.14f, 0.2f, 0.28f};
        float L = Ls[p%3], W = Wv[(p/3)%3];
        float xr = xx*ca + yy*sa;
        float yr = -xx*sa + yy*ca;
        float tp = powf(1.0f - fminf(fabsf(xr)/L, 1.0f), 1.5f);
        float yrw = yr / W;
        float core = expf(-0.5f*((xr/L)*(xr/L) + yrw*yrw));
        ridge[i] = tp * core * fmaxf(1.0f - yrw*yrw, 0.0f);
    }
    __syncthreads();
    int w = tid >> 5, lane = tid & 31;
    const float* rp = ridge + w*81;
    float s = 0.f;
    for (int j = lane; j < 81; j += 32) s += rp[j];
    #pragma unroll
    for (int o = 16; o > 0; o >>= 1) s += __shfl_xor_sync(0xffffffffu, s, o);
    float mean = s*(1.0f/81.0f);
    float a = 0.f;
    for (int j = lane; j < 81; j += 32) a += fabsf(rp[j]-mean);
    #pragma unroll
    for (int o = 16; o > 0; o >>= 1) a += __shfl_xor_sync(0xffffffffu, a, o);
    float den = fmaxf(a, 1e-6f);
    for (int j = lane; j < 81; j += 32)
        g_kern[w*81+j] = (rp[j]-mean)/den + 0.05f*pdelta[w*81+j];
}

// ---------------- K1: 768->8 1x1 conv + gelu; warp-granular 8-way K-split ----------------
// block = 8 warps; warp w owns K-chunk [96w,96w+96); lane owns one pixel pair.
// Every LDG.64 = 32 consecutive pairs = 256B = 2 lines (fully coalesced).
__global__ __launch_bounds__(256) void k1_gemm(const float* __restrict__ fm,
                                               const float* __restrict__ w,
                                               const float* __restrict__ bv){
    extern __shared__ ull dsm[];
    ull* ws   = dsm;            // 6144: (w,w) packed, c-major
    ull* part = dsm + NFC*NRC;  // 32*65 = 2080
    for (int i = threadIdx.x; i < NFC*NRC; i += 256){
        int c = i >> 3, r = i & 7;
        float v = w[r*NFC + c];
        ws[i] = pack2(v, v);
    }
    __syncthreads();
    int blk = blockIdx.x;                 // 512 blocks
    int b = blk >> 6, pg = blk & 63;      // image, pair-group
    int wp = threadIdx.x >> 5, lane = threadIdx.x & 31;
    int p = (pg*32 + lane) << 1;          // pixel index (pair)
    const float* x = fm + (size_t)b*NFC*HW + (size_t)(wp*96)*HW + p;
    const ull* wsp = ws + wp*96*8;
    ull acc[NRC];
    #pragma unroll
    for (int r = 0; r < NRC; r++) acc[r] = 0ull;
    #pragma unroll 8
    for (int c = 0; c < 96; c++){
        ull xv = *(const ull*)(x + (size_t)c*HW);
        const ull* wc = wsp + c*8;
        #pragma unroll
        for (int r = 0; r < NRC; r++) acc[r] = fma2(wc[r], xv, acc[r]);
    }
    ull* pr = part + lane*65 + wp*8;
    #pragma unroll
    for (int r = 0; r < NRC; r++) pr[r] = acc[r];
    __syncthreads();
    // reduce: thread i -> (channel r = i>>5, pair_local = i&31)
    int r = threadIdx.x >> 5, pl = threadIdx.x & 31;
    ull s = part[pl*65 + r];
    #pragma unroll
    for (int ww = 1; ww < 8; ww++) s = add2(s, part[pl*65 + ww*8 + r]);
    float lo, hi; unpack2(s, lo, hi);
    float bb = bv[r]; lo += bb; hi += bb;
    float2 v; v.x = geluf(lo); v.y = geluf(hi);
    int po = (pg*32 + pl) << 1;
    *(float2*)(g_cpre + (size_t)b*NRC*HW + (size_t)r*HW + po) = v;
}

// ---------------- K2: 3x3 conv 8->8 + gelu + channel stats (smem-tiled) ----------------
__global__ __launch_bounds__(256) void k2_conv3(const float* __restrict__ w,
                                                const float* __restrict__ bv){
    __shared__ float ws[NRC*NRC*9];
    __shared__ float bs[NRC];
    __shared__ float ts[NRC][18][19];
    for (int i = threadIdx.x; i < NRC*NRC*9; i += 256) ws[i] = w[i];
    if (threadIdx.x < NRC) bs[threadIdx.x] = bv[threadIdx.x];
    int blk = blockIdx.x; int b = blk >> 4, tile = blk & 15;
    int ty0 = (tile >> 2) << 4, tx0 = (tile & 3) << 4;
    const float* in = g_cpre + (size_t)b*NRC*HW;
    for (int i = threadIdx.x; i < NRC*18*18; i += 256){
        int ic = i / 324, rem = i % 324, ly = rem / 18, lx = rem % 18;
        int gy = ty0 - 1 + ly, gx = tx0 - 1 + lx;
        float v = 0.f;
        if (gy >= 0 && gy < 64 && gx >= 0 && gx < 64) v = in[ic*HW + gy*64 + gx];
        ts[ic][ly][lx] = v;
    }
    __syncthreads();
    int ty = threadIdx.x >> 4, tx = threadIdx.x & 15;
    float acc[NRC];
    #pragma unroll
    for (int r = 0; r < NRC; r++) acc[r] = bs[r];
    #pragma unroll
    for (int ic = 0; ic < NRC; ic++){
        #pragma unroll
        for (int dy = 0; dy < 3; dy++){
            #pragma unroll
            for (int dx = 0; dx < 3; dx++){
                float v = ts[ic][ty+dy][tx+dx];
                int tap = ic*9 + dy*3 + dx;
                #pragma unroll
                for (int oc = 0; oc < NRC; oc++)
                    acc[oc] = fmaf(ws[oc*72 + tap], v, acc[oc]);
            }
        }
    }
    int pix = (ty0+ty)*64 + (tx0+tx);
    int t = b*HW + pix;
    float m = 0.f, a = 0.f;
    float* oc_out = g_car + (size_t)b*NRC*HW + pix;
    #pragma unroll
    for (int r = 0; r < NRC; r++){
        float c = geluf(acc[r]);
        oc_out[r*HW] = c;
        m += c; a += fabsf(c);
    }
    g_cm[t] = m * 0.125f;
    g_dn[t] = a * 0.125f;
}

// ---------------- K3+K4 fused ----------------
__global__ __launch_bounds__(1024) void k3_hp_stats(){
    int b = blockIdx.x;
    __shared__ float cms[64*64];
    __shared__ float hps[66*68];
    __shared__ float red[5][32];
    int tid = threadIdx.x;
    const float* cm = g_cm + b*HW;
    float4 c4 = ((const float4*)cm)[tid];
    ((float4*)cms)[tid] = c4;
    if (tid < 66){
        hps[tid] = 0.f; hps[65*68 + tid] = 0.f;
        hps[tid*68] = 0.f; hps[tid*68 + 65] = 0.f;
    }
    __syncthreads();
    int y = tid >> 4, x0 = (tid & 15) << 2;
    float4 hp4;
    float* hp4p = &hp4.x;
    #pragma unroll
    for (int k = 0; k < 4; k++){
        int x = x0 + k;
        float s = 0.f;
        #pragma unroll
        for (int dy = -1; dy <= 1; dy++){
            int yy = y + dy; if (yy < 0 || yy > 63) continue;
            #pragma unroll
            for (int dx = -1; dx <= 1; dx++){
                int xx = x + dx; if (xx < 0 || xx > 63) continue;
                s += cms[yy*64 + xx];
            }
        }
        float h = cms[y*64 + x] - s*(1.0f/9.0f);
        hp4p[k] = h;
        hps[(y+1)*68 + (x+1)] = h;
    }
    ((float4*)(g_hp + b*HW))[tid] = hp4;
    __syncthreads();
    float cmn = 1e30f, cmx = -1e30f;
    float4 cs4;
    float* cs4p = &cs4.x;
    #pragma unroll
    for (int k = 0; k < 4; k++){
        int x = x0 + k;
        float s = 0.f;
        #pragma unroll
        for (int dy = 0; dy < 3; dy++)
            #pragma unroll
            for (int dx = 0; dx < 3; dx++)
                s += fabsf(hps[(y+dy)*68 + (x+dx)]);
        float cs = s*(1.0f/9.0f);
        cs4p[k] = cs;
        cmn = fminf(cmn, cs); cmx = fmaxf(cmx, cs);
    }
    ((float4*)(g_cs + b*HW))[tid] = cs4;
    float4 d4 = ((const float4*)(g_dn + b*HW))[tid];
    float dmn = fminf(fminf(d4.x, d4.y), fminf(d4.z, d4.w));
    float dmx = fmaxf(fmaxf(d4.x, d4.y), fmaxf(d4.z, d4.w));
    float ds  = (d4.x + d4.y) + (d4.z + d4.w);
    #pragma unroll
    for (int o = 16; o > 0; o >>= 1){
        cmn = fminf(cmn, __shfl_xor_sync(0xffffffffu, cmn, o));
        cmx = fmaxf(cmx, __shfl_xor_sync(0xffffffffu, cmx, o));
        dmn = fminf(dmn, __shfl_xor_sync(0xffffffffu, dmn, o));
        dmx = fmaxf(dmx, __shfl_xor_sync(0xffffffffu, dmx, o));
        ds += __shfl_xor_sync(0xffffffffu, ds, o);
    }
    int wid = tid >> 5, lane = tid & 31;
    if (lane == 0){ red[0][wid]=cmn; red[1][wid]=cmx; red[2][wid]=dmn; red[3][wid]=dmx; red[4][wid]=ds; }
    __syncthreads();
    if (tid < 32){
        cmn = red[0][tid]; cmx = red[1][tid]; dmn = red[2][tid]; dmx = red[3][tid]; ds = red[4][tid];
        #pragma unroll
        for (int o = 16; o > 0; o >>= 1){
            cmn = fminf(cmn, __shfl_xor_sync(0xffffffffu, cmn, o));
            cmx = fmaxf(cmx, __shfl_xor_sync(0xffffffffu, cmx, o));
            dmn = fminf(dmn, __shfl_xor_sync(0xffffffffu, dmn, o));
            dmx = fmaxf(dmx, __shfl_xor_sync(0xffffffffu, dmx, o));
            ds += __shfl_xor_sync(0xffffffffu, ds, o);
        }
        if (tid == 0){
            float* st = g_st + b*8;
            st[0]=cmn; st[1]=cmx; st[2]=dmn; st[3]=dmx; st[4]=ds*(1.0f/4096.0f);
        }
    }
}

// ---------------- K5: top2-softmax responses + ev/gate0 + erosion ----------------
__global__ __launch_bounds__(256) void k5_main(const float* __restrict__ theta,
                                               const float* __restrict__ length,
                                               const float* __restrict__ width,
                                               const float* __restrict__ plog){
    __shared__ float hps[24*24];
    __shared__ float kern[NP*81];
    __shared__ float m0s[20*20];
    int blk = blockIdx.x; int b = blk >> 4; int tile = blk & 15;
    int ty0 = (tile >> 2) << 4, tx0 = (tile & 3) << 4;

    const float* hp = g_hp + b*HW;
    for (int i = threadIdx.x; i < 576; i += 256){
        int ly = i/24, lx = i%24;
        int gy = ty0-4+ly, gx = tx0-4+lx;
        hps[i] = (gy>=0 && gy<64 && gx>=0 && gx<64) ? hp[gy*64+gx] : 0.f;
    }
    for (int i = threadIdx.x; i < NP*81; i += 256) kern[i] = g_kern[i];

    const float* st = g_st + b*8;
    float csmn = st[0], csmx = st[1], dmn = st[2], dmx = st[3];
    float m = fmaxf(st[4], 1e-6f);
    float csden = fmaxf(csmx - csmn, 1e-6f);
    float ddmn = dmn/m, ddmx = dmx/m;
    float dsden = fmaxf(ddmx - ddmn, 1e-6f);
    const float* csb = g_cs + b*HW; const float* dnb = g_dn + b*HW;
    for (int i = threadIdx.x; i < 400; i += 256){
        int ly = i/20, lx = i%20;
        int gy = ty0-2+ly, gx = tx0-2+lx;
        float v = 1.0f;
        if (gy>=0 && gy<64 && gx>=0 && gx<64){
            int gi = gy*64+gx;
            float csn = (csb[gi]-csmn)/csden;
            float dsn = (dnb[gi]/m - ddmn)/dsden;
            float ev = 0.65f*csn + 0.35f*dsn;
            v = (ev >= 0.2f) ? 1.0f : 0.0f;
        }
        m0s[i] = v;
    }
    __syncthreads();

    int ty = threadIdx.x >> 4, tx = threadIdx.x & 15;
    int gy = ty0 + ty, gx = tx0 + tx;
    int gi = gy*64 + gx; int t = b*HW + gi;
    {
        float csn = (csb[gi]-csmn)/csden;
        float dsn = (dnb[gi]/m - ddmn)/dsden;
        float ev = 0.65f*csn + 0.35f*dsn;
        g_g0[t] = sigm((ev - 0.2f)/0.08f);
    }
    {
        float e = 1.0f;
        #pragma unroll
        for (int dy = 0; dy < 5; dy++)
            #pragma unroll
            for (int dx = 0; dx < 5; dx++) e = fminf(e, m0s[(ty+dy)*20 + (tx+dx)]);
        g_er[t] = e;
    }
    float bias[NP];
    float ta = tanhf(theta[t]) * 3.14159265358979323846f;
    float lv = sigm(length[t])*0.85f + 0.25f;
    float wv = sigm(width[t])*0.22f + 0.08f;
    const float Ls[3] = {0.45f, 0.75f, 1.05f};
    const float Wv[3] = {0.14f, 0.2f, 0.28f};
    #pragma unroll
    for (int p = 0; p < NP; p++){
        float ori = (float)(6.283185307179586 * p / 8.0);
        float la = Ls[p%3], wa = Wv[(p/3)%3];
        float dl = lv - la, dw = wv - wa;
        bias[p] = plog[(size_t)b*NP*HW + p*HW + gi]
                + 1.25f*cosf(ta - ori)
                - dl*dl/0.08f
                - dw*dw/0.01f;
    }
    int i1 = 0; float m1 = bias[0];
    #pragma unroll
    for (int p = 1; p < NP; p++) if (bias[p] > m1){ m1 = bias[p]; i1 = p; }
    int i2 = (i1 == 0) ? 1 : 0; float m2 = -1e30f;
    #pragma unroll
    for (int p = 0; p < NP; p++) if (p != i1 && bias[p] > m2){ m2 = bias[p]; i2 = p; }
    float e2 = expf(m2 - m1);
    float inv = 1.0f/(1.0f + e2);
    float pw1 = inv, pw2 = e2*inv;

    const float* k1p = kern + i1*81;
    const float* k2p = kern + i2*81;
    float r1 = 0.f, r2v = 0.f;
    #pragma unroll
    for (int ky = 0; ky < 9; ky++){
        #pragma unroll
        for (int kx = 0; kx < 9; kx++){
            float v = hps[(ty+ky)*24 + (tx+kx)];
            r1  = fmaf(k1p[ky*9+kx], v, r1);
            r2v = fmaf(k2p[ky*9+kx], v, r2v);
        }
    }
    g_s0[t] = pw1*r1 + pw2*r2v;
}

// ---------------- K7: dilate/open combine + stroke gate + final ss (smem-tiled) ----------------
__global__ __launch_bounds__(256) void k7_comb(const float* __restrict__ obj,
                                               const float* __restrict__ alpha,
                                               const float* __restrict__ curv){
    __shared__ float ers[24*24];
    __shared__ float g0s[20*20];
    __shared__ float s0s[18*18];
    __shared__ float obs[18*18];
    int blk = blockIdx.x; int b = blk >> 4, tile = blk & 15;
    int ty0 = (tile >> 2) << 4, tx0 = (tile & 3) << 4;
    const float* er = g_er + b*HW;
    const float* g0 = g_g0 + b*HW;
    const float* s0 = g_s0 + b*HW;
    const float* ob = obj + b*HW;
    for (int i = threadIdx.x; i < 576; i += 256){
        int ly = i/24, lx = i%24;
        int gy = ty0-4+ly, gx = tx0-4+lx;
        ers[i] = (gy>=0 && gy<64 && gx>=0 && gx<64) ? er[gy*64+gx] : 0.f;
    }
    for (int i = threadIdx.x; i < 400; i += 256){
        int ly = i/20, lx = i%20;
        int gy = ty0-2+ly, gx = tx0-2+lx;
        g0s[i] = (gy>=0 && gy<64 && gx>=0 && gx<64) ? g0[gy*64+gx] : 0.f;
    }
    for (int i = threadIdx.x; i < 324; i += 256){
        int ly = i/18, lx = i%18;
        int gy = ty0-1+ly, gx = tx0-1+lx;
        bool in = (gy>=0 && gy<64 && gx>=0 && gx<64);
        s0s[i] = in ? s0[gy*64+gx] : 0.f;
        obs[i] = in ? sigm(ob[gy*64+gx]) : 0.f;
    }
    __syncthreads();
    int ty = threadIdx.x >> 4, tx = threadIdx.x & 15;
    float mask = 0.f;
    #pragma unroll
    for (int dy = 0; dy < 9; dy++)
        #pragma unroll
        for (int dx = 0; dx < 9; dx++) mask = fmaxf(mask, ers[(ty+dy)*24 + (tx+dx)]);
    float gate = 0.f;
    #pragma unroll
    for (int dy = 0; dy < 5; dy++)
        #pragma unroll
        for (int dx = 0; dx < 5; dx++) gate = fmaxf(gate, g0s[(ty+dy)*20 + (tx+dx)]);
    float blob = 0.f, ssum = 0.f;
    #pragma unroll
    for (int dy = 0; dy < 3; dy++)
        #pragma unroll
        for (int dx = 0; dx < 3; dx++){
            blob += obs[(ty+dy)*18 + (tx+dx)];
            ssum += s0s[(ty+dy)*18 + (tx+dx)];
        }
    blob *= (1.0f/9.0f);
    float ss1 = s0s[(ty+1)*18 + (tx+1)] - ssum*(1.0f/9.0f);
    int t = b*HW + (ty0+ty)*64 + (tx0+tx);
    float gatef = gate * mask;
    float dmean = fmaxf(g_st[b*8+4], 1e-6f);
    float dens = g_dn[t] / dmean;
    float sg = sigm(alpha[t]) * (blob * gatef) * (0.7f + 0.3f*fminf(fmaxf(dens, 0.f), 2.f));
    g_sf[t] = sg * ss1 * (1.0f + 0.15f*tanhf(curv[t]));
}

// ---------------- K8: feats -> 8 (gelu) -> 768; warp-granular 8-way fc-split ----------------
__global__ __launch_bounds__(256) void k8_out(const float* __restrict__ theta,
                                              const float* __restrict__ curv,
                                              const float* __restrict__ w1,
                                              const float* __restrict__ b1,
                                              const float* __restrict__ w2,
                                              const float* __restrict__ b2,
                                              float* __restrict__ out){
    extern __shared__ ull sh[];
    ull*   w2p = sh;                                  // 6144 packed pairs
    float* b2s = (float*)(sh + NFC*NRC);              // 768
    ull*   w1p = (ull*)(b2s + NFC);                   // 96
    float* b1s = (float*)(w1p + 96);                  // 8
    for (int i = threadIdx.x; i < NFC*NRC; i += 256){ float v = w2[i]; w2p[i] = pack2(v, v); }
    for (int i = threadIdx.x; i < NFC; i += 256) b2s[i] = b2[i];
    for (int i = threadIdx.x; i < 96; i += 256){ float v = w1[i]; w1p[i] = pack2(v, v); }
    if (threadIdx.x < 8) b1s[threadIdx.x] = b1[threadIdx.x];
    __syncthreads();

    int blk = blockIdx.x;                 // 512 blocks
    int b = blk >> 6, pg = blk & 63;
    int wp = threadIdx.x >> 5, lane = threadIdx.x & 31;
    int p = (pg*32 + lane) << 1;
    int base = b*HW + p;
    float2 ss = *(const float2*)(g_sf + base);
    float2 th = *(const float2*)(theta + base);
    float2 cv = *(const float2*)(curv + base);
    ull f[12];
    const float* car = g_car + (size_t)b*NRC*HW + p;
    #pragma unroll
    for (int r = 0; r < NRC; r++){
        float2 c = *(const float2*)(car + (size_t)r*HW);
        f[r] = pack2(c.x*ss.x, c.y*ss.y);
    }
    f[8] = pack2(ss.x, ss.y);
    const float PIF = 3.14159265358979323846f;
    float a0 = tanhf(th.x)*PIF, a1 = tanhf(th.y)*PIF;
    f[9]  = pack2(cosf(a0)*ss.x, cosf(a1)*ss.y);
    f[10] = pack2(sinf(a0)*ss.x, sinf(a1)*ss.y);
    f[11] = pack2(tanhf(cv.x)*ss.x, tanhf(cv.y)*ss.y);

    ull h[NRC];
    #pragma unroll
    for (int r = 0; r < NRC; r++){
        ull acc = pack2(b1s[r], b1s[r]);
        #pragma unroll
        for (int j = 0; j < 12; j++) acc = fma2(w1p[r*12+j], f[j], acc);
        float lo, hi; unpack2(acc, lo, hi);
        h[r] = pack2(geluf(lo), geluf(hi));
    }
    float* o = out + (size_t)b*NFC*HW + p;
    int fc0 = wp * 96;
    #pragma unroll 4
    for (int j = 0; j < 96; j++){
        int fc = fc0 + j;
        float bb = b2s[fc];
        ull acc = pack2(bb, bb);
        const ull* wr = w2p + fc*8;
        #pragma unroll
        for (int r = 0; r < NRC; r++) acc = fma2(wr[r], h[r], acc);
        float2 v; unpack2(acc, v.x, v.y);
        *(float2*)(o + (size_t)fc*HW) = v;
    }
}

// ---------------- host ----------------
extern "C" void kernel_launch(void* const* d_in, const int* in_sizes, int n_in,
                              void* d_out, int out_size){
    const float* fm    = (const float*)d_in[0];
    const float* theta = (const float*)d_in[1];
    const float* len   = (const float*)d_in[2];
    const float* wid   = (const float*)d_in[3];
    const float* curv  = (const float*)d_in[4];
    const float* alpha = (const float*)d_in[5];
    const float* obj   = (const float*)d_in[6];
    const float* plog  = (const float*)d_in[7];
    const float* fp1w  = (const float*)d_in[8];
    const float* fp1b  = (const float*)d_in[9];
    const float* fp2w  = (const float*)d_in[10];
    const float* fp2b  = (const float*)d_in[11];
    const float* pm1w  = (const float*)d_in[12];
    const float* pm1b  = (const float*)d_in[13];
    const float* pm2w  = (const float*)d_in[14];
    const float* pm2b  = (const float*)d_in[15];
    const float* pdel  = (const float*)d_in[16];

    cudaFuncSetAttribute(k1_gemm, cudaFuncAttributeMaxDynamicSharedMemorySize, 65792);
    cudaFuncSetAttribute(k8_out,  cudaFuncAttributeMaxDynamicSharedMemorySize, 53056);

    k0_bank<<<1,256>>>(pdel);
    k1_gemm<<<512,256,65792>>>(fm, fp1w, fp1b);
    k2_conv3<<<128,256>>>(fp2w, fp2b);
    k3_hp_stats<<<8,1024>>>();
    k5_main<<<128,256>>>(theta, len, wid, plog);
    k7_comb<<<128,256>>>(obj, alpha, curv);
    k8_out<<<512,256,53056>>>(theta, curv, pm1w, pm1b, pm2w, pm2b, (float*)d_out);
}

// round 9
// speedup vs baseline: 3.0450x; 1.0136x over previous
#include <cuda_runtime.h>
#include <math.h>

#define HW   4096
#define NB   8
#define NFC  768
#define NRC  8
#define NP   8

typedef unsigned long long ull;

// ---------------- scratch ----------------
__device__ float g_cpre[NB*NRC*HW];
__device__ float g_car [NB*NRC*HW];
__device__ float g_cm  [NB*HW];
__device__ float g_dn  [NB*HW];
__device__ float g_hp  [NB*HW];
__device__ float g_cs  [NB*HW];
__device__ float g_sf  [NB*HW];
__device__ float g_st  [NB*8];
__device__ float g_kern[NP*81];
__device__ float g_part[128*8];

// ---------------- helpers ----------------
__device__ __forceinline__ ull pack2(float lo, float hi){ ull r; asm("mov.b64 %0,{%1,%2};":"=l"(r):"f"(lo),"f"(hi)); return r; }
__device__ __forceinline__ ull fma2(ull a, ull b, ull c){ ull d; asm("fma.rn.f32x2 %0,%1,%2,%3;":"=l"(d):"l"(a),"l"(b),"l"(c)); return d; }
__device__ __forceinline__ ull add2(ull a, ull b){ ull d; asm("add.rn.f32x2 %0,%1,%2;":"=l"(d):"l"(a),"l"(b)); return d; }
__device__ __forceinline__ void unpack2(ull v, float&lo, float&hi){ asm("mov.b64 {%0,%1},%2;":"=f"(lo),"=f"(hi):"l"(v)); }
__device__ __forceinline__ float geluf(float x){ return 0.5f*x*(1.0f+erff(x*0.70710678118654752f)); }
__device__ __forceinline__ float sigm(float x){ return 1.0f/(1.0f+expf(-x)); }

// ---------------- K1: 768->8 1x1 conv + gelu; warp-granular 8-way K-split ----------------
__global__ __launch_bounds__(256) void k1_gemm(const float* __restrict__ fm,
                                               const float* __restrict__ w,
                                               const float* __restrict__ bv){
    extern __shared__ ull dsm[];
    ull* ws   = dsm;            // 6144
    ull* part = dsm + NFC*NRC;  // 32*65
    for (int i = threadIdx.x; i < NFC*NRC; i += 256){
        int c = i >> 3, r = i & 7;
        float v = w[r*NFC + c];
        ws[i] = pack2(v, v);
    }
    __syncthreads();
    int blk = blockIdx.x;
    int b = blk >> 6, pg = blk & 63;
    int wp = threadIdx.x >> 5, lane = threadIdx.x & 31;
    int p = (pg*32 + lane) << 1;
    const float* x = fm + (size_t)b*NFC*HW + (size_t)(wp*96)*HW + p;
    const ull* wsp = ws + wp*96*8;
    ull acc[NRC];
    #pragma unroll
    for (int r = 0; r < NRC; r++) acc[r] = 0ull;
    #pragma unroll 8
    for (int c = 0; c < 96; c++){
        ull xv = *(const ull*)(x + (size_t)c*HW);
        const ull* wc = wsp + c*8;
        #pragma unroll
        for (int r = 0; r < NRC; r++) acc[r] = fma2(wc[r], xv, acc[r]);
    }
    ull* pr = part + lane*65 + wp*8;
    #pragma unroll
    for (int r = 0; r < NRC; r++) pr[r] = acc[r];
    __syncthreads();
    int r = threadIdx.x >> 5, pl = threadIdx.x & 31;
    ull s = part[pl*65 + r];
    #pragma unroll
    for (int ww = 1; ww < 8; ww++) s = add2(s, part[pl*65 + ww*8 + r]);
    float lo, hi; unpack2(s, lo, hi);
    float bb = bv[r]; lo += bb; hi += bb;
    float2 v; v.x = geluf(lo); v.y = geluf(hi);
    int po = (pg*32 + pl) << 1;
    *(float2*)(g_cpre + (size_t)b*NRC*HW + (size_t)r*HW + po) = v;
}

// ---------------- K2: 3x3 conv 8->8 + gelu + stats; pair-pixel fma2, oc-split ----------------
// grid 128: 16x16 tile; 256 threads = 128 pixel-pairs x 2 oc-halves.
__global__ __launch_bounds__(256) void k2_conv3(const float* __restrict__ w,
                                                const float* __restrict__ bv){
    __shared__ ull  wsp[NRC*9*NRC];     // [ic*9+tap][oc] packed (w,w)
    __shared__ float bs[NRC];
    __shared__ float ts[NRC][18][18];
    __shared__ ull  pm[2][128];
    __shared__ ull  pa[2][128];
    for (int i = threadIdx.x; i < 576; i += 256){
        int ict = i >> 3, oc = i & 7;
        float v = w[oc*72 + ict];
        wsp[i] = pack2(v, v);
    }
    if (threadIdx.x < NRC) bs[threadIdx.x] = bv[threadIdx.x];
    int blk = blockIdx.x; int b = blk >> 4, tile = blk & 15;
    int ty0 = (tile >> 2) << 4, tx0 = (tile & 3) << 4;
    const float* in = g_cpre + (size_t)b*NRC*HW;
    for (int i = threadIdx.x; i < NRC*18*18; i += 256){
        int ic = i / 324, rem = i % 324, ly = rem / 18, lx = rem % 18;
        int gy = ty0 - 1 + ly, gx = tx0 - 1 + lx;
        float v = 0.f;
        if (gy >= 0 && gy < 64 && gx >= 0 && gx < 64) v = in[ic*HW + gy*64 + gx];
        ts[ic][ly][lx] = v;
    }
    __syncthreads();
    int pair = threadIdx.x & 127, half = threadIdx.x >> 7;
    int py = pair >> 3, px = (pair & 7) << 1;
    ull acc[4];
    #pragma unroll
    for (int j = 0; j < 4; j++){ float bb = bs[half*4+j]; acc[j] = pack2(bb, bb); }
    #pragma unroll
    for (int ic = 0; ic < NRC; ic++){
        #pragma unroll
        for (int dy = 0; dy < 3; dy++){
            #pragma unroll
            for (int dx = 0; dx < 3; dx++){
                float vlo = ts[ic][py+dy][px+dx];
                float vhi = ts[ic][py+dy][px+dx+1];
                ull vv = pack2(vlo, vhi);
                const ull* wc = wsp + (ic*9 + dy*3 + dx)*8 + half*4;
                #pragma unroll
                for (int j = 0; j < 4; j++) acc[j] = fma2(wc[j], vv, acc[j]);
            }
        }
    }
    int gp = (ty0+py)*64 + tx0+px;
    float mlo=0.f, mhi=0.f, alo=0.f, ahi=0.f;
    #pragma unroll
    for (int j = 0; j < 4; j++){
        float lo, hi; unpack2(acc[j], lo, hi);
        float clo = geluf(lo), chi = geluf(hi);
        float2 v; v.x = clo; v.y = chi;
        *(float2*)(g_car + (size_t)b*NRC*HW + (size_t)(half*4+j)*HW + gp) = v;
        mlo += clo; mhi += chi; alo += fabsf(clo); ahi += fabsf(chi);
    }
    pm[half][pair] = pack2(mlo, mhi);
    pa[half][pair] = pack2(alo, ahi);
    __syncthreads();
    if (threadIdx.x < 128){
        int pr = threadIdx.x;
        float m0,m1,a0,a1, n0,n1,b0,b1;
        unpack2(pm[0][pr], m0, m1); unpack2(pm[1][pr], n0, n1);
        unpack2(pa[0][pr], a0, a1); unpack2(pa[1][pr], b0, b1);
        int ppy = pr >> 3, ppx = (pr & 7) << 1;
        int gq = b*HW + (ty0+ppy)*64 + tx0+ppx;
        float2 cm; cm.x = (m0+n0)*0.125f; cm.y = (m1+n1)*0.125f;
        float2 dn; dn.x = (a0+b0)*0.125f; dn.y = (a1+b1)*0.125f;
        *(float2*)(g_cm + gq) = cm;
        *(float2*)(g_dn + gq) = dn;
    }
}

// ---------------- K3a: tiled hp/cs + per-tile partial stats ----------------
__global__ __launch_bounds__(256) void k3a_hp(){
    __shared__ float cms[20][20];
    __shared__ float hps[18][18];
    __shared__ float red[5][8];
    int blk = blockIdx.x; int b = blk >> 4, tile = blk & 15;
    int ty0 = (tile >> 2) << 4, tx0 = (tile & 3) << 4;
    const float* cm = g_cm + b*HW;
    for (int i = threadIdx.x; i < 400; i += 256){
        int ly = i/20, lx = i%20;
        int gy = ty0-2+ly, gx = tx0-2+lx;
        cms[ly][lx] = (gy>=0 && gy<64 && gx>=0 && gx<64) ? cm[gy*64+gx] : 0.f;
    }
    __syncthreads();
    for (int i = threadIdx.x; i < 324; i += 256){
        int ly = i/18, lx = i%18;
        int gy = ty0-1+ly, gx = tx0-1+lx;
        float v = 0.f;
        if (gy>=0 && gy<64 && gx>=0 && gx<64){
            float s = 0.f;
            #pragma unroll
            for (int dy = 0; dy < 3; dy++)
                #pragma unroll
                for (int dx = 0; dx < 3; dx++) s += cms[ly+dy][lx+dx];
            v = cms[ly+1][lx+1] - s*(1.0f/9.0f);
        }
        hps[ly][lx] = v;
    }
    __syncthreads();
    int ty = threadIdx.x >> 4, tx = threadIdx.x & 15;
    float s = 0.f;
    #pragma unroll
    for (int dy = 0; dy < 3; dy++)
        #pragma unroll
        for (int dx = 0; dx < 3; dx++) s += fabsf(hps[ty+dy][tx+dx]);
    float cs = s*(1.0f/9.0f);
    int gi = b*HW + (ty0+ty)*64 + (tx0+tx);
    g_hp[gi] = hps[ty+1][tx+1];
    g_cs[gi] = cs;
    float d = g_dn[gi];
    float cmn = cs, cmx = cs, dmn = d, dmx = d, ds = d;
    #pragma unroll
    for (int o = 16; o > 0; o >>= 1){
        cmn = fminf(cmn, __shfl_xor_sync(0xffffffffu, cmn, o));
        cmx = fmaxf(cmx, __shfl_xor_sync(0xffffffffu, cmx, o));
        dmn = fminf(dmn, __shfl_xor_sync(0xffffffffu, dmn, o));
        dmx = fmaxf(dmx, __shfl_xor_sync(0xffffffffu, dmx, o));
        ds += __shfl_xor_sync(0xffffffffu, ds, o);
    }
    int wd = threadIdx.x >> 5, lane = threadIdx.x & 31;
    if (lane == 0){ red[0][wd]=cmn; red[1][wd]=cmx; red[2][wd]=dmn; red[3][wd]=dmx; red[4][wd]=ds; }
    __syncthreads();
    if (threadIdx.x == 0){
        float c0=red[0][0], c1=red[1][0], d0=red[2][0], d1=red[3][0], dsu=red[4][0];
        for (int j = 1; j < 8; j++){
            c0 = fminf(c0, red[0][j]); c1 = fmaxf(c1, red[1][j]);
            d0 = fminf(d0, red[2][j]); d1 = fmaxf(d1, red[3][j]);
            dsu += red[4][j];
        }
        float* pp = g_part + blk*8;
        pp[0]=c0; pp[1]=c1; pp[2]=d0; pp[3]=d1; pp[4]=dsu;
    }
}

// ---------------- K3b: stats finisher (blocks 0-7) + bank build (block 8) ----------------
__global__ __launch_bounds__(256) void k3b_fin(const float* __restrict__ pdelta){
    if (blockIdx.x == 8){
        __shared__ float ridge[NP*81];
        int tid = threadIdx.x;
        for (int i = tid; i < NP*81; i += 256){
            int p = i/81, idx = i%81, ky = idx/9, kx = idx%9;
            float yy = -1.0f + 0.25f*ky, xx = -1.0f + 0.25f*kx;
            double ang = 6.283185307179586 * p / 8.0;
            float ca = (float)cos(ang), sa = (float)sin(ang);
            const float Ls[3] = {0.45f, 0.75f, 1.05f};
            const float Wv[3] = {0.14f, 0.2f, 0.28f};
            float L = Ls[p%3], W = Wv[(p/3)%3];
            float xr = xx*ca + yy*sa;
            float yr = -xx*sa + yy*ca;
            float tp = powf(1.0f - fminf(fabsf(xr)/L, 1.0f), 1.5f);
            float yrw = yr / W;
            float core = expf(-0.5f*((xr/L)*(xr/L) + yrw*yrw));
            ridge[i] = tp * core * fmaxf(1.0f - yrw*yrw, 0.0f);
        }
        __syncthreads();
        int w = tid >> 5, lane = tid & 31;
        const float* rp = ridge + w*81;
        float s = 0.f;
        for (int j = lane; j < 81; j += 32) s += rp[j];
        #pragma unroll
        for (int o = 16; o > 0; o >>= 1) s += __shfl_xor_sync(0xffffffffu, s, o);
        float mean = s*(1.0f/81.0f);
        float a = 0.f;
        for (int j = lane; j < 81; j += 32) a += fabsf(rp[j]-mean);
        #pragma unroll
        for (int o = 16; o > 0; o >>= 1) a += __shfl_xor_sync(0xffffffffu, a, o);
        float den = fmaxf(a, 1e-6f);
        for (int j = lane; j < 81; j += 32)
            g_kern[w*81+j] = (rp[j]-mean)/den + 0.05f*pdelta[w*81+j];
    } else {
        int b = blockIdx.x;
        if (threadIdx.x < 32){
            int lane = threadIdx.x;
            float v0=1e30f, v1=-1e30f, v2=1e30f, v3=-1e30f, v4=0.f;
            if (lane < 16){
                const float* pp = g_part + (b*16+lane)*8;
                v0=pp[0]; v1=pp[1]; v2=pp[2]; v3=pp[3]; v4=pp[4];
            }
            #pragma unroll
            for (int o = 8; o > 0; o >>= 1){
                v0 = fminf(v0, __shfl_down_sync(0xffffffffu, v0, o));
                v1 = fmaxf(v1, __shfl_down_sync(0xffffffffu, v1, o));
                v2 = fminf(v2, __shfl_down_sync(0xffffffffu, v2, o));
                v3 = fmaxf(v3, __shfl_down_sync(0xffffffffu, v3, o));
                v4 +=           __shfl_down_sync(0xffffffffu, v4, o);
            }
            if (lane == 0){
                float* st = g_st + b*8;
                st[0]=v0; st[1]=v1; st[2]=v2; st[3]=v3; st[4]=v4*(1.0f/4096.0f);
            }
        }
    }
}

// ---------------- K57: fused gating + responses + final ss ----------------
// per 16x16 tile, recompute ev/m0(h6), er(h4), g0(h2), s0/obs(h1) in smem.
__global__ __launch_bounds__(256) void k57_main(const float* __restrict__ theta,
                                                const float* __restrict__ length,
                                                const float* __restrict__ width,
                                                const float* __restrict__ plog,
                                                const float* __restrict__ obj,
                                                const float* __restrict__ alpha,
                                                const float* __restrict__ curv){
    __shared__ float hps[26*26];
    __shared__ float kern[NP*81];
    __shared__ float m0s[28*28];
    __shared__ float g0s[20*20];
    __shared__ float ers[24*24];
    __shared__ float s0s[18*18];
    __shared__ float obs[18*18];
    int blk = blockIdx.x; int b = blk >> 4, tile = blk & 15;
    int ty0 = (tile >> 2) << 4, tx0 = (tile & 3) << 4;

    const float* hp = g_hp + b*HW;
    for (int i = threadIdx.x; i < 676; i += 256){
        int ly = i/26, lx = i%26;
        int gy = ty0-5+ly, gx = tx0-5+lx;
        hps[i] = (gy>=0 && gy<64 && gx>=0 && gx<64) ? hp[gy*64+gx] : 0.f;
    }
    for (int i = threadIdx.x; i < NP*81; i += 256) kern[i] = g_kern[i];

    const float* st = g_st + b*8;
    float csmn = st[0], csmx = st[1], dmn = st[2], dmx = st[3];
    float m = fmaxf(st[4], 1e-6f);
    float csden = fmaxf(csmx - csmn, 1e-6f);
    float ddmn = dmn/m, ddmx = dmx/m;
    float dsden = fmaxf(ddmx - ddmn, 1e-6f);
    const float* csb = g_cs + b*HW; const float* dnb = g_dn + b*HW;
    // ev region halo 6 (28x28): m0 (OOB=1 neutral-min); g0 subset halo 2 (OOB=0)
    for (int i = threadIdx.x; i < 784; i += 256){
        int ly = i/28, lx = i%28;
        int gy = ty0-6+ly, gx = tx0-6+lx;
        float mv = 1.0f, gv = 0.0f;
        if (gy>=0 && gy<64 && gx>=0 && gx<64){
            int gi = gy*64+gx;
            float csn = (csb[gi]-csmn)/csden;
            float dsn = (dnb[gi]/m - ddmn)/dsden;
            float ev = 0.65f*csn + 0.35f*dsn;
            mv = (ev >= 0.2f) ? 1.0f : 0.0f;
            gv = sigm((ev - 0.2f)/0.08f);
        }
        m0s[i] = mv;
        if (ly >= 4 && ly < 24 && lx >= 4 && lx < 24)
            g0s[(ly-4)*20 + (lx-4)] = gv;
    }
    __syncthreads();
    // er halo 4 (24x24): min5 of m0; OOB er = 0
    for (int i = threadIdx.x; i < 576; i += 256){
        int ly = i/24, lx = i%24;
        int gy = ty0-4+ly, gx = tx0-4+lx;
        float e = 0.f;
        if (gy>=0 && gy<64 && gx>=0 && gx<64){
            e = 1.0f;
            #pragma unroll
            for (int dy = 0; dy < 5; dy++)
                #pragma unroll
                for (int dx = 0; dx < 5; dx++) e = fminf(e, m0s[(ly+dy)*28 + (lx+dx)]);
        }
        ers[i] = e;
    }
    // s0 + obs halo 1 (18x18)
    const float* ob = obj + b*HW;
    for (int i = threadIdx.x; i < 324; i += 256){
        int ly = i/18, lx = i%18;
        int gy = ty0-1+ly, gx = tx0-1+lx;
        float sv = 0.f, ov = 0.f;
        if (gy>=0 && gy<64 && gx>=0 && gx<64){
            int gi = gy*64+gx; int t = b*HW + gi;
            ov = sigm(ob[gi]);
            float bias[NP];
            float ta = tanhf(theta[t]) * 3.14159265358979323846f;
            float lv = sigm(length[t])*0.85f + 0.25f;
            float wv = sigm(width[t])*0.22f + 0.08f;
            const float Ls[3] = {0.45f, 0.75f, 1.05f};
            const float Wv[3] = {0.14f, 0.2f, 0.28f};
            #pragma unroll
            for (int p = 0; p < NP; p++){
                float ori = (float)(6.283185307179586 * p / 8.0);
                float la = Ls[p%3], wa = Wv[(p/3)%3];
                float dl = lv - la, dw = wv - wa;
                bias[p] = plog[(size_t)b*NP*HW + p*HW + gi]
                        + 1.25f*cosf(ta - ori)
                        - dl*dl/0.08f
                        - dw*dw/0.01f;
            }
            int i1 = 0; float m1 = bias[0];
            #pragma unroll
            for (int p = 1; p < NP; p++) if (bias[p] > m1){ m1 = bias[p]; i1 = p; }
            int i2 = (i1 == 0) ? 1 : 0; float m2 = -1e30f;
            #pragma unroll
            for (int p = 0; p < NP; p++) if (p != i1 && bias[p] > m2){ m2 = bias[p]; i2 = p; }
            float e2 = expf(m2 - m1);
            float inv = 1.0f/(1.0f + e2);
            float pw1 = inv, pw2 = e2*inv;
            const float* k1p = kern + i1*81;
            const float* k2p = kern + i2*81;
            float r1 = 0.f, r2v = 0.f;
            #pragma unroll
            for (int ky = 0; ky < 9; ky++){
                #pragma unroll
                for (int kx = 0; kx < 9; kx++){
                    float v = hps[(ly+ky)*26 + (lx+kx)];
                    r1  = fmaf(k1p[ky*9+kx], v, r1);
                    r2v = fmaf(k2p[ky*9+kx], v, r2v);
                }
            }
            sv = pw1*r1 + pw2*r2v;
        }
        s0s[i] = sv;
        obs[i] = ov;
    }
    __syncthreads();
    int ty = threadIdx.x >> 4, tx = threadIdx.x & 15;
    float mask = 0.f;
    #pragma unroll
    for (int dy = 0; dy < 9; dy++)
        #pragma unroll
        for (int dx = 0; dx < 9; dx++) mask = fmaxf(mask, ers[(ty+dy)*24 + (tx+dx)]);
    float gate = 0.f;
    #pragma unroll
    for (int dy = 0; dy < 5; dy++)
        #pragma unroll
        for (int dx = 0; dx < 5; dx++) gate = fmaxf(gate, g0s[(ty+dy)*20 + (tx+dx)]);
    float blob = 0.f, ssum = 0.f;
    #pragma unroll
    for (int dy = 0; dy < 3; dy++)
        #pragma unroll
        for (int dx = 0; dx < 3; dx++){
            blob += obs[(ty+dy)*18 + (tx+dx)];
            ssum += s0s[(ty+dy)*18 + (tx+dx)];
        }
    blob *= (1.0f/9.0f);
    float ss1 = s0s[(ty+1)*18 + (tx+1)] - ssum*(1.0f/9.0f);
    int t = b*HW + (ty0+ty)*64 + (tx0+tx);
    float gatef = gate * mask;
    float dmean = fmaxf(g_st[b*8+4], 1e-6f);
    float dens = g_dn[t] / dmean;
    float sg = sigm(alpha[t]) * (blob * gatef) * (0.7f + 0.3f*fminf(fmaxf(dens, 0.f), 2.f));
    g_sf[t] = sg * ss1 * (1.0f + 0.15f*tanhf(curv[t]));
}

// ---------------- K8: feats -> 8 (gelu) -> 768; warp-granular 8-way fc-split ----------------
__global__ __launch_bounds__(256) void k8_out(const float* __restrict__ theta,
                                              const float* __restrict__ curv,
                                              const float* __restrict__ w1,
                                              const float* __restrict__ b1,
                                              const float* __restrict__ w2,
                                              const float* __restrict__ b2,
                                              float* __restrict__ out){
    extern __shared__ ull sh[];
    ull*   w2p = sh;
    float* b2s = (float*)(sh + NFC*NRC);
    ull*   w1p = (ull*)(b2s + NFC);
    float* b1s = (float*)(w1p + 96);
    for (int i = threadIdx.x; i < NFC*NRC; i += 256){ float v = w2[i]; w2p[i] = pack2(v, v); }
    for (int i = threadIdx.x; i < NFC; i += 256) b2s[i] = b2[i];
    for (int i = threadIdx.x; i < 96; i += 256){ float v = w1[i]; w1p[i] = pack2(v, v); }
    if (threadIdx.x < 8) b1s[threadIdx.x] = b1[threadIdx.x];
    __syncthreads();

    int blk = blockIdx.x;
    int b = blk >> 6, pg = blk & 63;
    int wp = threadIdx.x >> 5, lane = threadIdx.x & 31;
    int p = (pg*32 + lane) << 1;
    int base = b*HW + p;
    float2 ss = *(const float2*)(g_sf + base);
    float2 th = *(const float2*)(theta + base);
    float2 cv = *(const float2*)(curv + base);
    ull f[12];
    const float* car = g_car + (size_t)b*NRC*HW + p;
    #pragma unroll
    for (int r = 0; r < NRC; r++){
        float2 c = *(const float2*)(car + (size_t)r*HW);
        f[r] = pack2(c.x*ss.x, c.y*ss.y);
    }
    f[8] = pack2(ss.x, ss.y);
    const float PIF = 3.14159265358979323846f;
    float a0 = tanhf(th.x)*PIF, a1 = tanhf(th.y)*PIF;
    f[9]  = pack2(cosf(a0)*ss.x, cosf(a1)*ss.y);
    f[10] = pack2(sinf(a0)*ss.x, sinf(a1)*ss.y);
    f[11] = pack2(tanhf(cv.x)*ss.x, tanhf(cv.y)*ss.y);

    ull h[NRC];
    #pragma unroll
    for (int r = 0; r < NRC; r++){
        ull acc = pack2(b1s[r], b1s[r]);
        #pragma unroll
        for (int j = 0; j < 12; j++) acc = fma2(w1p[r*12+j], f[j], acc);
        float lo, hi; unpack2(acc, lo, hi);
        h[r] = pack2(geluf(lo), geluf(hi));
    }
    float* o = out + (size_t)b*NFC*HW + p;
    int fc0 = wp * 96;
    #pragma unroll 4
    for (int j = 0; j < 96; j++){
        int fc = fc0 + j;
        float bb = b2s[fc];
        ull acc = pack2(bb, bb);
        const ull* wr = w2p + fc*8;
        #pragma unroll
        for (int r = 0; r < NRC; r++) acc = fma2(wr[r], h[r], acc);
        float2 v; unpack2(acc, v.x, v.y);
        *(float2*)(o + (size_t)fc*HW) = v;
    }
}

// ---------------- host ----------------
extern "C" void kernel_launch(void* const* d_in, const int* in_sizes, int n_in,
                              void* d_out, int out_size){
    const float* fm    = (const float*)d_in[0];
    const float* theta = (const float*)d_in[1];
    const float* len   = (const float*)d_in[2];
    const float* wid   = (const float*)d_in[3];
    const float* curv  = (const float*)d_in[4];
    const float* alpha = (const float*)d_in[5];
    const float* obj   = (const float*)d_in[6];
    const float* plog  = (const float*)d_in[7];
    const float* fp1w  = (const float*)d_in[8];
    const float* fp1b  = (const float*)d_in[9];
    const float* fp2w  = (const float*)d_in[10];
    const float* fp2b  = (const float*)d_in[11];
    const float* pm1w  = (const float*)d_in[12];
    const float* pm1b  = (const float*)d_in[13];
    const float* pm2w  = (const float*)d_in[14];
    const float* pm2b  = (const float*)d_in[15];
    const float* pdel  = (const float*)d_in[16];

    cudaFuncSetAttribute(k1_gemm, cudaFuncAttributeMaxDynamicSharedMemorySize, 65792);
    cudaFuncSetAttribute(k8_out,  cudaFuncAttributeMaxDynamicSharedMemorySize, 53056);

    k1_gemm<<<512,256,65792>>>(fm, fp1w, fp1b);
    k2_conv3<<<128,256>>>(fp2w, fp2b);
    k3a_hp<<<128,256>>>();
    k3b_fin<<<9,256>>>(pdel);
    k57_main<<<128,256>>>(theta, len, wid, plog, obj, alpha, curv);
    k8_out<<<512,256,53056>>>(theta, curv, pm1w, pm1b, pm2w, pm2b, (float*)d_out);
}

// round 10
// speedup vs baseline: 3.8413x; 1.2615x over previous
#include <cuda_runtime.h>
#include <math.h>

#define HW   4096
#define NB   8
#define NFC  768
#define NRC  8
#define NP   8

typedef unsigned long long ull;

// ---------------- scratch ----------------
__device__ float g_cpre[NB*NRC*HW];
__device__ float g_car [NB*NRC*HW];
__device__ float g_cm  [NB*HW];
__device__ float g_dn  [NB*HW];
__device__ float g_hp  [NB*HW];
__device__ float g_cs  [NB*HW];
__device__ float g_sf  [NB*HW];
__device__ float g_part[128*8];

// ---------------- helpers ----------------
__device__ __forceinline__ ull pack2(float lo, float hi){ ull r; asm("mov.b64 %0,{%1,%2};":"=l"(r):"f"(lo),"f"(hi)); return r; }
__device__ __forceinline__ ull fma2(ull a, ull b, ull c){ ull d; asm("fma.rn.f32x2 %0,%1,%2,%3;":"=l"(d):"l"(a),"l"(b),"l"(c)); return d; }
__device__ __forceinline__ ull add2(ull a, ull b){ ull d; asm("add.rn.f32x2 %0,%1,%2;":"=l"(d):"l"(a),"l"(b)); return d; }
__device__ __forceinline__ void unpack2(ull v, float&lo, float&hi){ asm("mov.b64 {%0,%1},%2;":"=f"(lo),"=f"(hi):"l"(v)); }
__device__ __forceinline__ float geluf(float x){ return 0.5f*x*(1.0f+erff(x*0.70710678118654752f)); }
__device__ __forceinline__ float sigm(float x){ return 1.0f/(1.0f+expf(-x)); }

// cos/sin(2*pi*p/8) as float (== (float)(double) values, incl. tiny non-zero eps terms)
__device__ __constant__ float c_ca[8] = {1.0f, 0.707106781f, 6.12323426e-17f, -0.707106781f,
                                         -1.0f, -0.707106781f, -1.83697015e-16f, 0.707106781f};
__device__ __constant__ float c_sa[8] = {0.0f, 0.707106781f, 1.0f, 0.707106781f,
                                         1.22464685e-16f, -0.707106781f, -1.0f, -0.707106781f};
__device__ __constant__ float c_ori[8] = {0.0f, 0.785398163f, 1.57079633f, 2.35619449f,
                                          3.14159265f, 3.92699082f, 4.71238898f, 5.49778714f};

// ---------------- K1: 768->8 1x1 conv + gelu; warp-granular 8-way K-split ----------------
// ws stored as float (24KB) -> 41.2KB dynamic smem -> 5 blocks/SM, single wave.
__global__ __launch_bounds__(256) void k1_gemm(const float* __restrict__ fm,
                                               const float* __restrict__ w,
                                               const float* __restrict__ bv){
    extern __shared__ char dsmc[];
    float* wsf = (float*)dsmc;                 // 6144 floats, c-major [c][r]
    ull*   part = (ull*)(dsmc + 24576);        // 32*65 ull
    for (int i = threadIdx.x; i < NFC*NRC; i += 256){
        int c = i >> 3, r = i & 7;
        wsf[i] = w[r*NFC + c];
    }
    __syncthreads();
    int blk = blockIdx.x;
    int b = blk >> 6, pg = blk & 63;
    int wp = threadIdx.x >> 5, lane = threadIdx.x & 31;
    int p = (pg*32 + lane) << 1;
    const float* x = fm + (size_t)b*NFC*HW + (size_t)(wp*96)*HW + p;
    const float* wc0 = wsf + wp*96*8;
    ull acc[NRC];
    #pragma unroll
    for (int r = 0; r < NRC; r++) acc[r] = 0ull;
    #pragma unroll 8
    for (int c = 0; c < 96; c++){
        ull xv = *(const ull*)(x + (size_t)c*HW);
        const float* wc = wc0 + c*8;
        #pragma unroll
        for (int r = 0; r < NRC; r++){
            float wv = wc[r];
            acc[r] = fma2(pack2(wv, wv), xv, acc[r]);
        }
    }
    ull* pr = part + lane*65 + wp*8;
    #pragma unroll
    for (int r = 0; r < NRC; r++) pr[r] = acc[r];
    __syncthreads();
    int r = threadIdx.x >> 5, pl = threadIdx.x & 31;
    ull s = part[pl*65 + r];
    #pragma unroll
    for (int ww = 1; ww < 8; ww++) s = add2(s, part[pl*65 + ww*8 + r]);
    float lo, hi; unpack2(s, lo, hi);
    float bb = bv[r]; lo += bb; hi += bb;
    float2 v; v.x = geluf(lo); v.y = geluf(hi);
    int po = (pg*32 + pl) << 1;
    *(float2*)(g_cpre + (size_t)b*NRC*HW + (size_t)r*HW + po) = v;
}

// ---------------- K2: 3x3 conv 8->8 + gelu + stats; pair-pixel fma2, oc-split ----------------
__global__ __launch_bounds__(256) void k2_conv3(const float* __restrict__ w,
                                                const float* __restrict__ bv){
    __shared__ ull  wsp[NRC*9*NRC];
    __shared__ float bs[NRC];
    __shared__ float ts[NRC][18][18];
    __shared__ ull  pm[2][128];
    __shared__ ull  pa[2][128];
    for (int i = threadIdx.x; i < 576; i += 256){
        int ict = i >> 3, oc = i & 7;
        float v = w[oc*72 + ict];
        wsp[i] = pack2(v, v);
    }
    if (threadIdx.x < NRC) bs[threadIdx.x] = bv[threadIdx.x];
    int blk = blockIdx.x; int b = blk >> 4, tile = blk & 15;
    int ty0 = (tile >> 2) << 4, tx0 = (tile & 3) << 4;
    const float* in = g_cpre + (size_t)b*NRC*HW;
    for (int i = threadIdx.x; i < NRC*18*18; i += 256){
        int ic = i / 324, rem = i % 324, ly = rem / 18, lx = rem % 18;
        int gy = ty0 - 1 + ly, gx = tx0 - 1 + lx;
        float v = 0.f;
        if (gy >= 0 && gy < 64 && gx >= 0 && gx < 64) v = in[ic*HW + gy*64 + gx];
        ts[ic][ly][lx] = v;
    }
    __syncthreads();
    int pair = threadIdx.x & 127, half = threadIdx.x >> 7;
    int py = pair >> 3, px = (pair & 7) << 1;
    ull acc[4];
    #pragma unroll
    for (int j = 0; j < 4; j++){ float bb = bs[half*4+j]; acc[j] = pack2(bb, bb); }
    #pragma unroll
    for (int ic = 0; ic < NRC; ic++){
        #pragma unroll
        for (int dy = 0; dy < 3; dy++){
            #pragma unroll
            for (int dx = 0; dx < 3; dx++){
                float vlo = ts[ic][py+dy][px+dx];
                float vhi = ts[ic][py+dy][px+dx+1];
                ull vv = pack2(vlo, vhi);
                const ull* wc = wsp + (ic*9 + dy*3 + dx)*8 + half*4;
                #pragma unroll
                for (int j = 0; j < 4; j++) acc[j] = fma2(wc[j], vv, acc[j]);
            }
        }
    }
    int gp = (ty0+py)*64 + tx0+px;
    float mlo=0.f, mhi=0.f, alo=0.f, ahi=0.f;
    #pragma unroll
    for (int j = 0; j < 4; j++){
        float lo, hi; unpack2(acc[j], lo, hi);
        float clo = geluf(lo), chi = geluf(hi);
        float2 v; v.x = clo; v.y = chi;
        *(float2*)(g_car + (size_t)b*NRC*HW + (size_t)(half*4+j)*HW + gp) = v;
        mlo += clo; mhi += chi; alo += fabsf(clo); ahi += fabsf(chi);
    }
    pm[half][pair] = pack2(mlo, mhi);
    pa[half][pair] = pack2(alo, ahi);
    __syncthreads();
    if (threadIdx.x < 128){
        int pr = threadIdx.x;
        float m0,m1,a0,a1, n0,n1,b0,b1;
        unpack2(pm[0][pr], m0, m1); unpack2(pm[1][pr], n0, n1);
        unpack2(pa[0][pr], a0, a1); unpack2(pa[1][pr], b0, b1);
        int ppy = pr >> 3, ppx = (pr & 7) << 1;
        int gq = b*HW + (ty0+ppy)*64 + tx0+ppx;
        float2 cm; cm.x = (m0+n0)*0.125f; cm.y = (m1+n1)*0.125f;
        float2 dn; dn.x = (a0+b0)*0.125f; dn.y = (a1+b1)*0.125f;
        *(float2*)(g_cm + gq) = cm;
        *(float2*)(g_dn + gq) = dn;
    }
}

// ---------------- K3a: tiled hp/cs + per-tile partial stats ----------------
__global__ __launch_bounds__(256) void k3a_hp(){
    __shared__ float cms[20][20];
    __shared__ float hps[18][18];
    __shared__ float red[5][8];
    int blk = blockIdx.x; int b = blk >> 4, tile = blk & 15;
    int ty0 = (tile >> 2) << 4, tx0 = (tile & 3) << 4;
    const float* cm = g_cm + b*HW;
    for (int i = threadIdx.x; i < 400; i += 256){
        int ly = i/20, lx = i%20;
        int gy = ty0-2+ly, gx = tx0-2+lx;
        cms[ly][lx] = (gy>=0 && gy<64 && gx>=0 && gx<64) ? cm[gy*64+gx] : 0.f;
    }
    __syncthreads();
    for (int i = threadIdx.x; i < 324; i += 256){
        int ly = i/18, lx = i%18;
        int gy = ty0-1+ly, gx = tx0-1+lx;
        float v = 0.f;
        if (gy>=0 && gy<64 && gx>=0 && gx<64){
            float s = 0.f;
            #pragma unroll
            for (int dy = 0; dy < 3; dy++)
                #pragma unroll
                for (int dx = 0; dx < 3; dx++) s += cms[ly+dy][lx+dx];
            v = cms[ly+1][lx+1] - s*(1.0f/9.0f);
        }
        hps[ly][lx] = v;
    }
    __syncthreads();
    int ty = threadIdx.x >> 4, tx = threadIdx.x & 15;
    float s = 0.f;
    #pragma unroll
    for (int dy = 0; dy < 3; dy++)
        #pragma unroll
        for (int dx = 0; dx < 3; dx++) s += fabsf(hps[ty+dy][tx+dx]);
    float cs = s*(1.0f/9.0f);
    int gi = b*HW + (ty0+ty)*64 + (tx0+tx);
    g_hp[gi] = hps[ty+1][tx+1];
    g_cs[gi] = cs;
    float d = g_dn[gi];
    float cmn = cs, cmx = cs, dmn = d, dmx = d, ds = d;
    #pragma unroll
    for (int o = 16; o > 0; o >>= 1){
        cmn = fminf(cmn, __shfl_xor_sync(0xffffffffu, cmn, o));
        cmx = fmaxf(cmx, __shfl_xor_sync(0xffffffffu, cmx, o));
        dmn = fminf(dmn, __shfl_xor_sync(0xffffffffu, dmn, o));
        dmx = fmaxf(dmx, __shfl_xor_sync(0xffffffffu, dmx, o));
        ds += __shfl_xor_sync(0xffffffffu, ds, o);
    }
    int wd = threadIdx.x >> 5, lane = threadIdx.x & 31;
    if (lane == 0){ red[0][wd]=cmn; red[1][wd]=cmx; red[2][wd]=dmn; red[3][wd]=dmx; red[4][wd]=ds; }
    __syncthreads();
    if (threadIdx.x == 0){
        float c0=red[0][0], c1=red[1][0], d0=red[2][0], d1=red[3][0], dsu=red[4][0];
        for (int j = 1; j < 8; j++){
            c0 = fminf(c0, red[0][j]); c1 = fmaxf(c1, red[1][j]);
            d0 = fminf(d0, red[2][j]); d1 = fmaxf(d1, red[3][j]);
            dsu += red[4][j];
        }
        float* pp = g_part + blk*8;
        pp[0]=c0; pp[1]=c1; pp[2]=d0; pp[3]=d1; pp[4]=dsu;
    }
}

// ---------------- K57: inline bank + stats + gating + responses + final ss ----------------
__global__ __launch_bounds__(256) void k57_main(const float* __restrict__ theta,
                                                const float* __restrict__ length,
                                                const float* __restrict__ width,
                                                const float* __restrict__ plog,
                                                const float* __restrict__ obj,
                                                const float* __restrict__ alpha,
                                                const float* __restrict__ curv,
                                                const float* __restrict__ pdelta){
    __shared__ float hps[26*26];
    __shared__ float kern[NP*81];
    __shared__ float m0s[28*28];
    __shared__ float g0s[20*20];
    __shared__ float ers[24*24];
    __shared__ float s0s[18*18];
    __shared__ float obs[18*18];
    __shared__ float st_s[5];
    int blk = blockIdx.x; int b = blk >> 4, tile = blk & 15;
    int ty0 = (tile >> 2) << 4, tx0 = (tile & 3) << 4;
    int tid = threadIdx.x;

    const float* hp = g_hp + b*HW;
    for (int i = tid; i < 676; i += 256){
        int ly = i/26, lx = i%26;
        int gy = ty0-5+ly, gx = tx0-5+lx;
        hps[i] = (gy>=0 && gy<64 && gx>=0 && gx<64) ? hp[gy*64+gx] : 0.f;
    }
    // ridge bank (fast math: const trig, t*sqrt(t))
    const float Ls[3] = {0.45f, 0.75f, 1.05f};
    const float Wv[3] = {0.14f, 0.2f, 0.28f};
    for (int i = tid; i < NP*81; i += 256){
        int p = i/81, idx = i%81, ky = idx/9, kx = idx%9;
        float yy = -1.0f + 0.25f*ky, xx = -1.0f + 0.25f*kx;
        float ca = c_ca[p], sa = c_sa[p];
        float L = Ls[p%3], W = Wv[(p/3)%3];
        float xr = xx*ca + yy*sa;
        float yr = -xx*sa + yy*ca;
        float tt = 1.0f - fminf(fabsf(xr)/L, 1.0f);
        float tp = tt*sqrtf(tt);
        float yrw = yr / W;
        float core = expf(-0.5f*((xr/L)*(xr/L) + yrw*yrw));
        kern[i] = tp * core * fmaxf(1.0f - yrw*yrw, 0.0f);
    }
    __syncthreads();
    // per-warp normalize (warp = prototype), in place
    {
        int w = tid >> 5, lane = tid & 31;
        float* rp = kern + w*81;
        float s = 0.f;
        for (int j = lane; j < 81; j += 32) s += rp[j];
        #pragma unroll
        for (int o = 16; o > 0; o >>= 1) s += __shfl_xor_sync(0xffffffffu, s, o);
        float mean = s*(1.0f/81.0f);
        float a = 0.f;
        for (int j = lane; j < 81; j += 32) a += fabsf(rp[j]-mean);
        #pragma unroll
        for (int o = 16; o > 0; o >>= 1) a += __shfl_xor_sync(0xffffffffu, a, o);
        float den = fmaxf(a, 1e-6f);
        for (int j = lane; j < 81; j += 32)
            rp[j] = (rp[j]-mean)/den + 0.05f*pdelta[w*81+j];
    }
    // warp 0: per-image stats from k3a partials
    if (tid < 32){
        int lane = tid;
        float v0=1e30f, v1=-1e30f, v2=1e30f, v3=-1e30f, v4=0.f;
        if (lane < 16){
            const float* pp = g_part + (b*16+lane)*8;
            v0=pp[0]; v1=pp[1]; v2=pp[2]; v3=pp[3]; v4=pp[4];
        }
        #pragma unroll
        for (int o = 8; o > 0; o >>= 1){
            v0 = fminf(v0, __shfl_down_sync(0xffffffffu, v0, o));
            v1 = fmaxf(v1, __shfl_down_sync(0xffffffffu, v1, o));
            v2 = fminf(v2, __shfl_down_sync(0xffffffffu, v2, o));
            v3 = fmaxf(v3, __shfl_down_sync(0xffffffffu, v3, o));
            v4 +=           __shfl_down_sync(0xffffffffu, v4, o);
        }
        if (lane == 0){
            st_s[0]=v0; st_s[1]=v1; st_s[2]=v2; st_s[3]=v3; st_s[4]=v4*(1.0f/4096.0f);
        }
    }
    __syncthreads();

    float csmn = st_s[0], csmx = st_s[1], dmn = st_s[2], dmx = st_s[3];
    float m = fmaxf(st_s[4], 1e-6f);
    float csden = fmaxf(csmx - csmn, 1e-6f);
    float ddmn = dmn/m, ddmx = dmx/m;
    float dsden = fmaxf(ddmx - ddmn, 1e-6f);
    const float* csb = g_cs + b*HW; const float* dnb = g_dn + b*HW;
    for (int i = tid; i < 784; i += 256){
        int ly = i/28, lx = i%28;
        int gy = ty0-6+ly, gx = tx0-6+lx;
        float mv = 1.0f, gv = 0.0f;
        if (gy>=0 && gy<64 && gx>=0 && gx<64){
            int gi = gy*64+gx;
            float csn = (csb[gi]-csmn)/csden;
            float dsn = (dnb[gi]/m - ddmn)/dsden;
            float ev = 0.65f*csn + 0.35f*dsn;
            mv = (ev >= 0.2f) ? 1.0f : 0.0f;
            gv = sigm((ev - 0.2f)/0.08f);
        }
        m0s[i] = mv;
        if (ly >= 4 && ly < 24 && lx >= 4 && lx < 24)
            g0s[(ly-4)*20 + (lx-4)] = gv;
    }
    __syncthreads();
    for (int i = tid; i < 576; i += 256){
        int ly = i/24, lx = i%24;
        int gy = ty0-4+ly, gx = tx0-4+lx;
        float e = 0.f;
        if (gy>=0 && gy<64 && gx>=0 && gx<64){
            e = 1.0f;
            #pragma unroll
            for (int dy = 0; dy < 5; dy++)
                #pragma unroll
                for (int dx = 0; dx < 5; dx++) e = fminf(e, m0s[(ly+dy)*28 + (lx+dx)]);
        }
        ers[i] = e;
    }
    const float* ob = obj + b*HW;
    for (int i = tid; i < 324; i += 256){
        int ly = i/18, lx = i%18;
        int gy = ty0-1+ly, gx = tx0-1+lx;
        float sv = 0.f, ov = 0.f;
        if (gy>=0 && gy<64 && gx>=0 && gx<64){
            int gi = gy*64+gx; int t = b*HW + gi;
            ov = sigm(ob[gi]);
            float bias[NP];
            float ta = tanhf(theta[t]) * 3.14159265358979323846f;
            float lv = sigm(length[t])*0.85f + 0.25f;
            float wv = sigm(width[t])*0.22f + 0.08f;
            #pragma unroll
            for (int p = 0; p < NP; p++){
                float la = Ls[p%3], wa = Wv[(p/3)%3];
                float dl = lv - la, dw = wv - wa;
                bias[p] = plog[(size_t)b*NP*HW + p*HW + gi]
                        + 1.25f*cosf(ta - c_ori[p])
                        - dl*dl/0.08f
                        - dw*dw/0.01f;
            }
            int i1 = 0; float m1 = bias[0];
            #pragma unroll
            for (int p = 1; p < NP; p++) if (bias[p] > m1){ m1 = bias[p]; i1 = p; }
            int i2 = (i1 == 0) ? 1 : 0; float m2 = -1e30f;
            #pragma unroll
            for (int p = 0; p < NP; p++) if (p != i1 && bias[p] > m2){ m2 = bias[p]; i2 = p; }
            float e2 = expf(m2 - m1);
            float inv = 1.0f/(1.0f + e2);
            float pw1 = inv, pw2 = e2*inv;
            const float* k1p = kern + i1*81;
            const float* k2p = kern + i2*81;
            float r1 = 0.f, r2v = 0.f;
            #pragma unroll
            for (int ky = 0; ky < 9; ky++){
                #pragma unroll
                for (int kx = 0; kx < 9; kx++){
                    float v = hps[(ly+ky)*26 + (lx+kx)];
                    r1  = fmaf(k1p[ky*9+kx], v, r1);
                    r2v = fmaf(k2p[ky*9+kx], v, r2v);
                }
            }
            sv = pw1*r1 + pw2*r2v;
        }
        s0s[i] = sv;
        obs[i] = ov;
    }
    __syncthreads();
    int ty = tid >> 4, tx = tid & 15;
    float mask = 0.f;
    #pragma unroll
    for (int dy = 0; dy < 9; dy++)
        #pragma unroll
        for (int dx = 0; dx < 9; dx++) mask = fmaxf(mask, ers[(ty+dy)*24 + (tx+dx)]);
    float gate = 0.f;
    #pragma unroll
    for (int dy = 0; dy < 5; dy++)
        #pragma unroll
        for (int dx = 0; dx < 5; dx++) gate = fmaxf(gate, g0s[(ty+dy)*20 + (tx+dx)]);
    float blob = 0.f, ssum = 0.f;
    #pragma unroll
    for (int dy = 0; dy < 3; dy++)
        #pragma unroll
        for (int dx = 0; dx < 3; dx++){
            blob += obs[(ty+dy)*18 + (tx+dx)];
            ssum += s0s[(ty+dy)*18 + (tx+dx)];
        }
    blob *= (1.0f/9.0f);
    float ss1 = s0s[(ty+1)*18 + (tx+1)] - ssum*(1.0f/9.0f);
    int t = b*HW + (ty0+ty)*64 + (tx0+tx);
    float gatef = gate * mask;
    float dmean = fmaxf(st_s[4], 1e-6f);
    float dens = g_dn[t] / dmean;
    float sg = sigm(alpha[t]) * (blob * gatef) * (0.7f + 0.3f*fminf(fmaxf(dens, 0.f), 2.f));
    g_sf[t] = sg * ss1 * (1.0f + 0.15f*tanhf(curv[t]));
}

// ---------------- K8: feats -> 8 (gelu) -> 768; warp-granular 8-way fc-split ----------------
__global__ __launch_bounds__(256) void k8_out(const float* __restrict__ theta,
                                              const float* __restrict__ curv,
                                              const float* __restrict__ w1,
                                              const float* __restrict__ b1,
                                              const float* __restrict__ w2,
                                              const float* __restrict__ b2,
                                              float* __restrict__ out){
    extern __shared__ ull sh[];
    ull*   w2p = sh;
    float* b2s = (float*)(sh + NFC*NRC);
    ull*   w1p = (ull*)(b2s + NFC);
    float* b1s = (float*)(w1p + 96);
    for (int i = threadIdx.x; i < NFC*NRC; i += 256){ float v = w2[i]; w2p[i] = pack2(v, v); }
    for (int i = threadIdx.x; i < NFC; i += 256) b2s[i] = b2[i];
    for (int i = threadIdx.x; i < 96; i += 256){ float v = w1[i]; w1p[i] = pack2(v, v); }
    if (threadIdx.x < 8) b1s[threadIdx.x] = b1[threadIdx.x];
    __syncthreads();

    int blk = blockIdx.x;
    int b = blk >> 6, pg = blk & 63;
    int wp = threadIdx.x >> 5, lane = threadIdx.x & 31;
    int p = (pg*32 + lane) << 1;
    int base = b*HW + p;
    float2 ss = *(const float2*)(g_sf + base);
    float2 th = *(const float2*)(theta + base);
    float2 cv = *(const float2*)(curv + base);
    ull f[12];
    const float* car = g_car + (size_t)b*NRC*HW + p;
    #pragma unroll
    for (int r = 0; r < NRC; r++){
        float2 c = *(const float2*)(car + (size_t)r*HW);
        f[r] = pack2(c.x*ss.x, c.y*ss.y);
    }
    f[8] = pack2(ss.x, ss.y);
    const float PIF = 3.14159265358979323846f;
    float a0 = tanhf(th.x)*PIF, a1 = tanhf(th.y)*PIF;
    f[9]  = pack2(cosf(a0)*ss.x, cosf(a1)*ss.y);
    f[10] = pack2(sinf(a0)*ss.x, sinf(a1)*ss.y);
    f[11] = pack2(tanhf(cv.x)*ss.x, tanhf(cv.y)*ss.y);

    ull h[NRC];
    #pragma unroll
    for (int r = 0; r < NRC; r++){
        ull acc = pack2(b1s[r], b1s[r]);
        #pragma unroll
        for (int j = 0; j < 12; j++) acc = fma2(w1p[r*12+j], f[j], acc);
        float lo, hi; unpack2(acc, lo, hi);
        h[r] = pack2(geluf(lo), geluf(hi));
    }
    float* o = out + (size_t)b*NFC*HW + p;
    int fc0 = wp * 96;
    #pragma unroll 4
    for (int j = 0; j < 96; j++){
        int fc = fc0 + j;
        float bb = b2s[fc];
        ull acc = pack2(bb, bb);
        const ull* wr = w2p + fc*8;
        #pragma unroll
        for (int r = 0; r < NRC; r++) acc = fma2(wr[r], h[r], acc);
        float2 v; unpack2(acc, v.x, v.y);
        *(float2*)(o + (size_t)fc*HW) = v;
    }
}

// ---------------- host ----------------
extern "C" void kernel_launch(void* const* d_in, const int* in_sizes, int n_in,
                              void* d_out, int out_size){
    const float* fm    = (const float*)d_in[0];
    const float* theta = (const float*)d_in[1];
    const float* len   = (const float*)d_in[2];
    const float* wid   = (const float*)d_in[3];
    const float* curv  = (const float*)d_in[4];
    const float* alpha = (const float*)d_in[5];
    const float* obj   = (const float*)d_in[6];
    const float* plog  = (const float*)d_in[7];
    const float* fp1w  = (const float*)d_in[8];
    const float* fp1b  = (const float*)d_in[9];
    const float* fp2w  = (const float*)d_in[10];
    const float* fp2b  = (const float*)d_in[11];
    const float* pm1w  = (const float*)d_in[12];
    const float* pm1b  = (const float*)d_in[13];
    const float* pm2w  = (const float*)d_in[14];
    const float* pm2b  = (const float*)d_in[15];
    const float* pdel  = (const float*)d_in[16];

    cudaFuncSetAttribute(k8_out,  cudaFuncAttributeMaxDynamicSharedMemorySize, 53056);

    k1_gemm<<<512,256,41216>>>(fm, fp1w, fp1b);
    k2_conv3<<<128,256>>>(fp2w, fp2b);
    k3a_hp<<<128,256>>>();
    k57_main<<<128,256>>>(theta, len, wid, plog, obj, alpha, curv, pdel);
    k8_out<<<512,256,53056>>>(theta, curv, pm1w, pm1b, pm2w, pm2b, (float*)d_out);
}

// round 11
// speedup vs baseline: 4.3391x; 1.1296x over previous
#include <cuda_runtime.h>
#include <math.h>

#define HW   4096
#define NB   8
#define NFC  768
#define NRC  8
#define NP   8

typedef unsigned long long ull;

// ---------------- scratch ----------------
__device__ float g_cpre[NB*NRC*HW];
__device__ float g_car [NB*NRC*HW];
__device__ float g_cm  [NB*HW];
__device__ float g_dn  [NB*HW];
__device__ float g_hp  [NB*HW];
__device__ float g_cs  [NB*HW];
__device__ float g_sf  [NB*HW];
__device__ float g_part[128*8];
__device__ float g_kern[NP*81];

// ---------------- helpers ----------------
__device__ __forceinline__ ull pack2(float lo, float hi){ ull r; asm("mov.b64 %0,{%1,%2};":"=l"(r):"f"(lo),"f"(hi)); return r; }
__device__ __forceinline__ ull fma2(ull a, ull b, ull c){ ull d; asm("fma.rn.f32x2 %0,%1,%2,%3;":"=l"(d):"l"(a),"l"(b),"l"(c)); return d; }
__device__ __forceinline__ ull add2(ull a, ull b){ ull d; asm("add.rn.f32x2 %0,%1,%2;":"=l"(d):"l"(a),"l"(b)); return d; }
__device__ __forceinline__ void unpack2(ull v, float&lo, float&hi){ asm("mov.b64 {%0,%1},%2;":"=f"(lo),"=f"(hi):"l"(v)); }
__device__ __forceinline__ float geluf(float x){ return 0.5f*x*(1.0f+erff(x*0.70710678118654752f)); }
__device__ __forceinline__ float sigm(float x){ return 1.0f/(1.0f+expf(-x)); }
__device__ __forceinline__ float sigmf_(float x){ return 1.0f/(1.0f+__expf(-x)); }

// cos/sin(2*pi*p/8) as float
__device__ __constant__ float c_ca[8] = {1.0f, 0.707106781f, 6.12323426e-17f, -0.707106781f,
                                         -1.0f, -0.707106781f, -1.83697015e-16f, 0.707106781f};
__device__ __constant__ float c_sa[8] = {0.0f, 0.707106781f, 1.0f, 0.707106781f,
                                         1.22464685e-16f, -0.707106781f, -1.0f, -0.707106781f};

// ---------------- K1: 768->8 1x1 conv + gelu; warp-granular 8-way K-split ----------------
// block 0 additionally builds the prototype kernel bank into g_kern (hidden in the wave).
__global__ __launch_bounds__(256) void k1_gemm(const float* __restrict__ fm,
                                               const float* __restrict__ w,
                                               const float* __restrict__ bv,
                                               const float* __restrict__ pdelta){
    extern __shared__ char dsmc[];
    float* wsf = (float*)dsmc;                 // 6144 floats, c-major [c][r]
    ull*   part = (ull*)(dsmc + 24576);        // 32*65 ull
    __shared__ float ridgeS[NP*81];
    for (int i = threadIdx.x; i < NFC*NRC; i += 256){
        int c = i >> 3, r = i & 7;
        wsf[i] = w[r*NFC + c];
    }
    __syncthreads();
    int blk = blockIdx.x;
    int b = blk >> 6, pg = blk & 63;
    int wp = threadIdx.x >> 5, lane = threadIdx.x & 31;
    int p = (pg*32 + lane) << 1;
    const float* x = fm + (size_t)b*NFC*HW + (size_t)(wp*96)*HW + p;
    const float* wc0 = wsf + wp*96*8;
    ull acc[NRC];
    #pragma unroll
    for (int r = 0; r < NRC; r++) acc[r] = 0ull;
    #pragma unroll 8
    for (int c = 0; c < 96; c++){
        ull xv = *(const ull*)(x + (size_t)c*HW);
        const float* wc = wc0 + c*8;
        #pragma unroll
        for (int r = 0; r < NRC; r++){
            float wv = wc[r];
            acc[r] = fma2(pack2(wv, wv), xv, acc[r]);
        }
    }
    ull* pr = part + lane*65 + wp*8;
    #pragma unroll
    for (int r = 0; r < NRC; r++) pr[r] = acc[r];
    __syncthreads();
    int r = threadIdx.x >> 5, pl = threadIdx.x & 31;
    ull s = part[pl*65 + r];
    #pragma unroll
    for (int ww = 1; ww < 8; ww++) s = add2(s, part[pl*65 + ww*8 + r]);
    float lo, hi; unpack2(s, lo, hi);
    float bb = bv[r]; lo += bb; hi += bb;
    float2 v; v.x = geluf(lo); v.y = geluf(hi);
    int po = (pg*32 + pl) << 1;
    *(float2*)(g_cpre + (size_t)b*NRC*HW + (size_t)r*HW + po) = v;

    // ---- block 0: prototype bank build ----
    if (blockIdx.x == 0){
        const float Ls[3] = {0.45f, 0.75f, 1.05f};
        const float Wv[3] = {0.14f, 0.2f, 0.28f};
        for (int i = threadIdx.x; i < NP*81; i += 256){
            int pp = i/81, idx = i%81, ky = idx/9, kx = idx%9;
            float yy = -1.0f + 0.25f*ky, xx = -1.0f + 0.25f*kx;
            float ca = c_ca[pp], sa = c_sa[pp];
            float L = Ls[pp%3], W = Wv[(pp/3)%3];
            float xr = xx*ca + yy*sa;
            float yr = -xx*sa + yy*ca;
            float xl = __fdividef(xr, L);
            float tt = 1.0f - fminf(fabsf(xl), 1.0f);
            float tp = tt*sqrtf(tt);
            float yrw = __fdividef(yr, W);
            float core = __expf(-0.5f*(xl*xl + yrw*yrw));
            ridgeS[i] = tp * core * fmaxf(1.0f - yrw*yrw, 0.0f);
        }
        __syncthreads();
        int wpp = threadIdx.x >> 5, ln = threadIdx.x & 31;
        float* rp = ridgeS + wpp*81;
        float su = 0.f;
        for (int j = ln; j < 81; j += 32) su += rp[j];
        #pragma unroll
        for (int o = 16; o > 0; o >>= 1) su += __shfl_xor_sync(0xffffffffu, su, o);
        float mean = su*(1.0f/81.0f);
        float a = 0.f;
        for (int j = ln; j < 81; j += 32) a += fabsf(rp[j]-mean);
        #pragma unroll
        for (int o = 16; o > 0; o >>= 1) a += __shfl_xor_sync(0xffffffffu, a, o);
        float den = fmaxf(a, 1e-6f);
        for (int j = ln; j < 81; j += 32)
            g_kern[wpp*81+j] = (rp[j]-mean)/den + 0.05f*pdelta[wpp*81+j];
    }
}

// ---------------- K2: 3x3 conv 8->8 + gelu + stats; pair-pixel fma2, oc-split ----------------
__global__ __launch_bounds__(256) void k2_conv3(const float* __restrict__ w,
                                                const float* __restrict__ bv){
    __shared__ ull  wsp[NRC*9*NRC];
    __shared__ float bs[NRC];
    __shared__ float ts[NRC][18][18];
    __shared__ ull  pm[2][128];
    __shared__ ull  pa[2][128];
    for (int i = threadIdx.x; i < 576; i += 256){
        int ict = i >> 3, oc = i & 7;
        float v = w[oc*72 + ict];
        wsp[i] = pack2(v, v);
    }
    if (threadIdx.x < NRC) bs[threadIdx.x] = bv[threadIdx.x];
    int blk = blockIdx.x; int b = blk >> 4, tile = blk & 15;
    int ty0 = (tile >> 2) << 4, tx0 = (tile & 3) << 4;
    const float* in = g_cpre + (size_t)b*NRC*HW;
    for (int i = threadIdx.x; i < NRC*18*18; i += 256){
        int ic = i / 324, rem = i % 324, ly = rem / 18, lx = rem % 18;
        int gy = ty0 - 1 + ly, gx = tx0 - 1 + lx;
        float v = 0.f;
        if (gy >= 0 && gy < 64 && gx >= 0 && gx < 64) v = in[ic*HW + gy*64 + gx];
        ts[ic][ly][lx] = v;
    }
    __syncthreads();
    int pair = threadIdx.x & 127, half = threadIdx.x >> 7;
    int py = pair >> 3, px = (pair & 7) << 1;
    ull acc[4];
    #pragma unroll
    for (int j = 0; j < 4; j++){ float bb = bs[half*4+j]; acc[j] = pack2(bb, bb); }
    #pragma unroll
    for (int ic = 0; ic < NRC; ic++){
        #pragma unroll
        for (int dy = 0; dy < 3; dy++){
            #pragma unroll
            for (int dx = 0; dx < 3; dx++){
                float vlo = ts[ic][py+dy][px+dx];
                float vhi = ts[ic][py+dy][px+dx+1];
                ull vv = pack2(vlo, vhi);
                const ull* wc = wsp + (ic*9 + dy*3 + dx)*8 + half*4;
                #pragma unroll
                for (int j = 0; j < 4; j++) acc[j] = fma2(wc[j], vv, acc[j]);
            }
        }
    }
    int gp = (ty0+py)*64 + tx0+px;
    float mlo=0.f, mhi=0.f, alo=0.f, ahi=0.f;
    #pragma unroll
    for (int j = 0; j < 4; j++){
        float lo, hi; unpack2(acc[j], lo, hi);
        float clo = geluf(lo), chi = geluf(hi);
        float2 v; v.x = clo; v.y = chi;
        *(float2*)(g_car + (size_t)b*NRC*HW + (size_t)(half*4+j)*HW + gp) = v;
        mlo += clo; mhi += chi; alo += fabsf(clo); ahi += fabsf(chi);
    }
    pm[half][pair] = pack2(mlo, mhi);
    pa[half][pair] = pack2(alo, ahi);
    __syncthreads();
    if (threadIdx.x < 128){
        int pr = threadIdx.x;
        float m0,m1,a0,a1, n0,n1,b0,b1;
        unpack2(pm[0][pr], m0, m1); unpack2(pm[1][pr], n0, n1);
        unpack2(pa[0][pr], a0, a1); unpack2(pa[1][pr], b0, b1);
        int ppy = pr >> 3, ppx = (pr & 7) << 1;
        int gq = b*HW + (ty0+ppy)*64 + tx0+ppx;
        float2 cm; cm.x = (m0+n0)*0.125f; cm.y = (m1+n1)*0.125f;
        float2 dn; dn.x = (a0+b0)*0.125f; dn.y = (a1+b1)*0.125f;
        *(float2*)(g_cm + gq) = cm;
        *(float2*)(g_dn + gq) = dn;
    }
}

// ---------------- K3a: tiled hp/cs + per-tile partial stats ----------------
__global__ __launch_bounds__(256) void k3a_hp(){
    __shared__ float cms[20][20];
    __shared__ float hps[18][18];
    __shared__ float red[5][8];
    int blk = blockIdx.x; int b = blk >> 4, tile = blk & 15;
    int ty0 = (tile >> 2) << 4, tx0 = (tile & 3) << 4;
    const float* cm = g_cm + b*HW;
    for (int i = threadIdx.x; i < 400; i += 256){
        int ly = i/20, lx = i%20;
        int gy = ty0-2+ly, gx = tx0-2+lx;
        cms[ly][lx] = (gy>=0 && gy<64 && gx>=0 && gx<64) ? cm[gy*64+gx] : 0.f;
    }
    __syncthreads();
    for (int i = threadIdx.x; i < 324; i += 256){
        int ly = i/18, lx = i%18;
        int gy = ty0-1+ly, gx = tx0-1+lx;
        float v = 0.f;
        if (gy>=0 && gy<64 && gx>=0 && gx<64){
            float s = 0.f;
            #pragma unroll
            for (int dy = 0; dy < 3; dy++)
                #pragma unroll
                for (int dx = 0; dx < 3; dx++) s += cms[ly+dy][lx+dx];
            v = cms[ly+1][lx+1] - s*(1.0f/9.0f);
        }
        hps[ly][lx] = v;
    }
    __syncthreads();
    int ty = threadIdx.x >> 4, tx = threadIdx.x & 15;
    float s = 0.f;
    #pragma unroll
    for (int dy = 0; dy < 3; dy++)
        #pragma unroll
        for (int dx = 0; dx < 3; dx++) s += fabsf(hps[ty+dy][tx+dx]);
    float cs = s*(1.0f/9.0f);
    int gi = b*HW + (ty0+ty)*64 + (tx0+tx);
    g_hp[gi] = hps[ty+1][tx+1];
    g_cs[gi] = cs;
    float d = g_dn[gi];
    float cmn = cs, cmx = cs, dmn = d, dmx = d, ds = d;
    #pragma unroll
    for (int o = 16; o > 0; o >>= 1){
        cmn = fminf(cmn, __shfl_xor_sync(0xffffffffu, cmn, o));
        cmx = fmaxf(cmx, __shfl_xor_sync(0xffffffffu, cmx, o));
        dmn = fminf(dmn, __shfl_xor_sync(0xffffffffu, dmn, o));
        dmx = fmaxf(dmx, __shfl_xor_sync(0xffffffffu, dmx, o));
        ds += __shfl_xor_sync(0xffffffffu, ds, o);
    }
    int wd = threadIdx.x >> 5, lane = threadIdx.x & 31;
    if (lane == 0){ red[0][wd]=cmn; red[1][wd]=cmx; red[2][wd]=dmn; red[3][wd]=dmx; red[4][wd]=ds; }
    __syncthreads();
    if (threadIdx.x == 0){
        float c0=red[0][0], c1=red[1][0], d0=red[2][0], d1=red[3][0], dsu=red[4][0];
        for (int j = 1; j < 8; j++){
            c0 = fminf(c0, red[0][j]); c1 = fmaxf(c1, red[1][j]);
            d0 = fminf(d0, red[2][j]); d1 = fmaxf(d1, red[3][j]);
            dsu += red[4][j];
        }
        float* pp = g_part + blk*8;
        pp[0]=c0; pp[1]=c1; pp[2]=d0; pp[3]=d1; pp[4]=dsu;
    }
}

// ---------------- K57: stats + gating + responses + final ss; 512 threads ----------------
__global__ __launch_bounds__(512) void k57_main(const float* __restrict__ theta,
                                                const float* __restrict__ length,
                                                const float* __restrict__ width,
                                                const float* __restrict__ plog,
                                                const float* __restrict__ obj,
                                                const float* __restrict__ alpha,
                                                const float* __restrict__ curv){
    __shared__ float hps[26*26];
    __shared__ float kern[NP*81];
    __shared__ float m0s[28*28];
    __shared__ float g0s[20*20];
    __shared__ float ers[24*24];
    __shared__ float s0s[18*18];
    __shared__ float obs[18*18];
    __shared__ float cmin[24*28];    // col-min5 of m0s
    __shared__ float cmax[16*24];    // col-max9 of ers
    __shared__ float gcol[16*20];    // col-max5 of g0s
    __shared__ float st_s[5];
    int blk = blockIdx.x; int b = blk >> 4, tile = blk & 15;
    int ty0 = (tile >> 2) << 4, tx0 = (tile & 3) << 4;
    int tid = threadIdx.x;

    const float* hp = g_hp + b*HW;
    for (int i = tid; i < 676; i += 512){
        int ly = i/26, lx = i%26;
        int gy = ty0-5+ly, gx = tx0-5+lx;
        hps[i] = (gy>=0 && gy<64 && gx>=0 && gx<64) ? hp[gy*64+gx] : 0.f;
    }
    for (int i = tid; i < NP*81; i += 512) kern[i] = g_kern[i];
    if (tid < 32){
        int lane = tid;
        float v0=1e30f, v1=-1e30f, v2=1e30f, v3=-1e30f, v4=0.f;
        if (lane < 16){
            const float* pp = g_part + (b*16+lane)*8;
            v0=pp[0]; v1=pp[1]; v2=pp[2]; v3=pp[3]; v4=pp[4];
        }
        #pragma unroll
        for (int o = 8; o > 0; o >>= 1){
            v0 = fminf(v0, __shfl_down_sync(0xffffffffu, v0, o));
            v1 = fmaxf(v1, __shfl_down_sync(0xffffffffu, v1, o));
            v2 = fminf(v2, __shfl_down_sync(0xffffffffu, v2, o));
            v3 = fmaxf(v3, __shfl_down_sync(0xffffffffu, v3, o));
            v4 +=           __shfl_down_sync(0xffffffffu, v4, o);
        }
        if (lane == 0){
            st_s[0]=v0; st_s[1]=v1; st_s[2]=v2; st_s[3]=v3; st_s[4]=v4*(1.0f/4096.0f);
        }
    }
    __syncthreads();

    float csmn = st_s[0], csmx = st_s[1], dmn = st_s[2], dmx = st_s[3];
    float m = fmaxf(st_s[4], 1e-6f);
    float csden = fmaxf(csmx - csmn, 1e-6f);
    float ddmn = dmn/m, ddmx = dmx/m;
    float dsden = fmaxf(ddmx - ddmn, 1e-6f);
    const float* csb = g_cs + b*HW; const float* dnb = g_dn + b*HW;
    for (int i = tid; i < 784; i += 512){
        int ly = i/28, lx = i%28;
        int gy = ty0-6+ly, gx = tx0-6+lx;
        float mv = 1.0f, gv = 0.0f;
        if (gy>=0 && gy<64 && gx>=0 && gx<64){
            int gi = gy*64+gx;
            float csn = (csb[gi]-csmn)/csden;
            float dsn = (dnb[gi]/m - ddmn)/dsden;
            float ev = 0.65f*csn + 0.35f*dsn;
            mv = (ev >= 0.2f) ? 1.0f : 0.0f;
            gv = sigmf_((ev - 0.2f)*12.5f);
        }
        m0s[i] = mv;
        if (ly >= 4 && ly < 24 && lx >= 4 && lx < 24)
            g0s[(ly-4)*20 + (lx-4)] = gv;
    }
    __syncthreads();
    // column min5 of m0s: cmin[ly][lx], ly 0..23, lx 0..27
    for (int i = tid; i < 672; i += 512){
        int ly = i/28, lx = i%28;
        float e = m0s[ly*28+lx];
        #pragma unroll
        for (int dy = 1; dy < 5; dy++) e = fminf(e, m0s[(ly+dy)*28+lx]);
        cmin[i] = e;
    }
    __syncthreads();
    // er: row min5 + OOB zero
    for (int i = tid; i < 576; i += 512){
        int ly = i/24, lx = i%24;
        int gy = ty0-4+ly, gx = tx0-4+lx;
        float e = 0.f;
        if (gy>=0 && gy<64 && gx>=0 && gx<64){
            e = cmin[ly*28+lx];
            #pragma unroll
            for (int dx = 1; dx < 5; dx++) e = fminf(e, cmin[ly*28+lx+dx]);
        }
        ers[i] = e;
    }
    // s0 + obs halo 1 (18x18)
    const float* ob = obj + b*HW;
    const float Ls[3] = {0.45f, 0.75f, 1.05f};
    const float Wv[3] = {0.14f, 0.2f, 0.28f};
    for (int i = tid; i < 324; i += 512){
        int ly = i/18, lx = i%18;
        int gy = ty0-1+ly, gx = tx0-1+lx;
        float sv = 0.f, ov = 0.f;
        if (gy>=0 && gy<64 && gx>=0 && gx<64){
            int gi = gy*64+gx; int t = b*HW + gi;
            ov = sigmf_(ob[gi]);
            float bias[NP];
            float ta = tanhf(theta[t]) * 3.14159265358979323846f;
            float cta, sta; __sincosf(ta, &sta, &cta);
            float lv = sigmf_(length[t])*0.85f + 0.25f;
            float wv = sigmf_(width[t])*0.22f + 0.08f;
            #pragma unroll
            for (int p = 0; p < NP; p++){
                float la = Ls[p%3], wa = Wv[(p/3)%3];
                float dl = lv - la, dw = wv - wa;
                bias[p] = plog[(size_t)b*NP*HW + p*HW + gi]
                        + 1.25f*(cta*c_ca[p] + sta*c_sa[p])
                        - dl*dl*12.5f
                        - dw*dw*100.0f;
            }
            int i1 = 0; float m1 = bias[0];
            #pragma unroll
            for (int p = 1; p < NP; p++) if (bias[p] > m1){ m1 = bias[p]; i1 = p; }
            int i2 = (i1 == 0) ? 1 : 0; float m2 = -1e30f;
            #pragma unroll
            for (int p = 0; p < NP; p++) if (p != i1 && bias[p] > m2){ m2 = bias[p]; i2 = p; }
            float e2 = __expf(m2 - m1);
            float inv = 1.0f/(1.0f + e2);
            float pw1 = inv, pw2 = e2*inv;
            const float* k1p = kern + i1*81;
            const float* k2p = kern + i2*81;
            float r1 = 0.f, r2v = 0.f;
            #pragma unroll
            for (int ky = 0; ky < 9; ky++){
                #pragma unroll
                for (int kx = 0; kx < 9; kx++){
                    float v = hps[(ly+ky)*26 + (lx+kx)];
                    r1  = fmaf(k1p[ky*9+kx], v, r1);
                    r2v = fmaf(k2p[ky*9+kx], v, r2v);
                }
            }
            sv = pw1*r1 + pw2*r2v;
        }
        s0s[i] = sv;
        obs[i] = ov;
    }
    __syncthreads();
    // column passes: cmax (max9 over ers rows), gcol (max5 over g0s rows)
    for (int i = tid; i < 704; i += 512){
        if (i < 384){
            int ty = i/24, lx = i%24;
            float e = ers[ty*24+lx];
            #pragma unroll
            for (int dy = 1; dy < 9; dy++) e = fmaxf(e, ers[(ty+dy)*24+lx]);
            cmax[i] = e;
        } else {
            int j = i - 384;
            int ty = j/20, lx = j%20;
            float g = g0s[ty*20+lx];
            #pragma unroll
            for (int dy = 1; dy < 5; dy++) g = fmaxf(g, g0s[(ty+dy)*20+lx]);
            gcol[j] = g;
        }
    }
    __syncthreads();
    if (tid < 256){
        int ty = tid >> 4, tx = tid & 15;
        float mask = cmax[ty*24+tx];
        #pragma unroll
        for (int dx = 1; dx < 9; dx++) mask = fmaxf(mask, cmax[ty*24+tx+dx]);
        float gate = gcol[ty*20+tx];
        #pragma unroll
        for (int dx = 1; dx < 5; dx++) gate = fmaxf(gate, gcol[ty*20+tx+dx]);
        float blob = 0.f, ssum = 0.f;
        #pragma unroll
        for (int dy = 0; dy < 3; dy++)
            #pragma unroll
            for (int dx = 0; dx < 3; dx++){
                blob += obs[(ty+dy)*18 + (tx+dx)];
                ssum += s0s[(ty+dy)*18 + (tx+dx)];
            }
        blob *= (1.0f/9.0f);
        float ss1 = s0s[(ty+1)*18 + (tx+1)] - ssum*(1.0f/9.0f);
        int t = b*HW + (ty0+ty)*64 + (tx0+tx);
        float gatef = gate * mask;
        float dmean = fmaxf(st_s[4], 1e-6f);
        float dens = g_dn[t] / dmean;
        float sg = sigmf_(alpha[t]) * (blob * gatef) * (0.7f + 0.3f*fminf(fmaxf(dens, 0.f), 2.f));
        g_sf[t] = sg * ss1 * (1.0f + 0.15f*tanhf(curv[t]));
    }
}

// ---------------- K8: feats -> 8 (gelu) -> 768; warp-granular 8-way fc-split ----------------
__global__ __launch_bounds__(256) void k8_out(const float* __restrict__ theta,
                                              const float* __restrict__ curv,
                                              const float* __restrict__ w1,
                                              const float* __restrict__ b1,
                                              const float* __restrict__ w2,
                                              const float* __restrict__ b2,
                                              float* __restrict__ out){
    extern __shared__ ull sh[];
    ull*   w2p = sh;
    float* b2s = (float*)(sh + NFC*NRC);
    ull*   w1p = (ull*)(b2s + NFC);
    float* b1s = (float*)(w1p + 96);
    for (int i = threadIdx.x; i < NFC*NRC; i += 256){ float v = w2[i]; w2p[i] = pack2(v, v); }
    for (int i = threadIdx.x; i < NFC; i += 256) b2s[i] = b2[i];
    for (int i = threadIdx.x; i < 96; i += 256){ float v = w1[i]; w1p[i] = pack2(v, v); }
    if (threadIdx.x < 8) b1s[threadIdx.x] = b1[threadIdx.x];
    __syncthreads();

    int blk = blockIdx.x;
    int b = blk >> 6, pg = blk & 63;
    int wp = threadIdx.x >> 5, lane = threadIdx.x & 31;
    int p = (pg*32 + lane) << 1;
    int base = b*HW + p;
    float2 ss = *(const float2*)(g_sf + base);
    float2 th = *(const float2*)(theta + base);
    float2 cv = *(const float2*)(curv + base);
    ull f[12];
    const float* car = g_car + (size_t)b*NRC*HW + p;
    #pragma unroll
    for (int r = 0; r < NRC; r++){
        float2 c = *(const float2*)(car + (size_t)r*HW);
        f[r] = pack2(c.x*ss.x, c.y*ss.y);
    }
    f[8] = pack2(ss.x, ss.y);
    const float PIF = 3.14159265358979323846f;
    float a0 = tanhf(th.x)*PIF, a1 = tanhf(th.y)*PIF;
    f[9]  = pack2(cosf(a0)*ss.x, cosf(a1)*ss.y);
    f[10] = pack2(sinf(a0)*ss.x, sinf(a1)*ss.y);
    f[11] = pack2(tanhf(cv.x)*ss.x, tanhf(cv.y)*ss.y);

    ull h[NRC];
    #pragma unroll
    for (int r = 0; r < NRC; r++){
        ull acc = pack2(b1s[r], b1s[r]);
        #pragma unroll
        for (int j = 0; j < 12; j++) acc = fma2(w1p[r*12+j], f[j], acc);
        float lo, hi; unpack2(acc, lo, hi);
        h[r] = pack2(geluf(lo), geluf(hi));
    }
    float* o = out + (size_t)b*NFC*HW + p;
    int fc0 = wp * 96;
    #pragma unroll 4
    for (int j = 0; j < 96; j++){
        int fc = fc0 + j;
        float bb = b2s[fc];
        ull acc = pack2(bb, bb);
        const ull* wr = w2p + fc*8;
        #pragma unroll
        for (int r = 0; r < NRC; r++) acc = fma2(wr[r], h[r], acc);
        float2 v; unpack2(acc, v.x, v.y);
        *(float2*)(o + (size_t)fc*HW) = v;
    }
}

// ---------------- host ----------------
extern "C" void kernel_launch(void* const* d_in, const int* in_sizes, int n_in,
                              void* d_out, int out_size){
    const float* fm    = (const float*)d_in[0];
    const float* theta = (const float*)d_in[1];
    const float* len   = (const float*)d_in[2];
    const float* wid   = (const float*)d_in[3];
    const float* curv  = (const float*)d_in[4];
    const float* alpha = (const float*)d_in[5];
    const float* obj   = (const float*)d_in[6];
    const float* plog  = (const float*)d_in[7];
    const float* fp1w  = (const float*)d_in[8];
    const float* fp1b  = (const float*)d_in[9];
    const float* fp2w  = (const float*)d_in[10];
    const float* fp2b  = (const float*)d_in[11];
    const float* pm1w  = (const float*)d_in[12];
    const float* pm1b  = (const float*)d_in[13];
    const float* pm2w  = (const float*)d_in[14];
    const float* pm2b  = (const float*)d_in[15];
    const float* pdel  = (const float*)d_in[16];

    cudaFuncSetAttribute(k1_gemm, cudaFuncAttributeMaxDynamicSharedMemorySize, 41216);
    cudaFuncSetAttribute(k8_out,  cudaFuncAttributeMaxDynamicSharedMemorySize, 53056);

    k1_gemm<<<512,256,41216>>>(fm, fp1w, fp1b, pdel);
    k2_conv3<<<128,256>>>(fp2w, fp2b);
    k3a_hp<<<128,256>>>();
    k57_main<<<128,512>>>(theta, len, wid, plog, obj, alpha, curv);
    k8_out<<<512,256,53056>>>(theta, curv, pm1w, pm1b, pm2w, pm2b, (float*)d_out);
}

// round 12
// speedup vs baseline: 4.3699x; 1.0071x over previous
#include <cuda_runtime.h>
#include <math.h>

#define HW   4096
#define NB   8
#define NFC  768
#define NRC  8
#define NP   8

typedef unsigned long long ull;

// ---------------- scratch ----------------
__device__ float g_cpre[NB*NRC*HW];
__device__ float g_car [NB*NRC*HW];
__device__ float g_dn  [NB*HW];
__device__ float g_hp  [NB*HW];
__device__ float g_cs  [NB*HW];
__device__ float g_sf  [NB*HW];
__device__ float g_part[128*8];
__device__ float g_kern[NP*81];

// ---------------- helpers ----------------
__device__ __forceinline__ ull pack2(float lo, float hi){ ull r; asm("mov.b64 %0,{%1,%2};":"=l"(r):"f"(lo),"f"(hi)); return r; }
__device__ __forceinline__ ull fma2(ull a, ull b, ull c){ ull d; asm("fma.rn.f32x2 %0,%1,%2,%3;":"=l"(d):"l"(a),"l"(b),"l"(c)); return d; }
__device__ __forceinline__ ull add2(ull a, ull b){ ull d; asm("add.rn.f32x2 %0,%1,%2;":"=l"(d):"l"(a),"l"(b)); return d; }
__device__ __forceinline__ void unpack2(ull v, float&lo, float&hi){ asm("mov.b64 {%0,%1},%2;":"=f"(lo),"=f"(hi):"l"(v)); }
__device__ __forceinline__ float geluf(float x){ return 0.5f*x*(1.0f+erff(x*0.70710678118654752f)); }
__device__ __forceinline__ float sigmf_(float x){ return 1.0f/(1.0f+__expf(-x)); }

__device__ __constant__ float c_ca[8] = {1.0f, 0.707106781f, 6.12323426e-17f, -0.707106781f,
                                         -1.0f, -0.707106781f, -1.83697015e-16f, 0.707106781f};
__device__ __constant__ float c_sa[8] = {0.0f, 0.707106781f, 1.0f, 0.707106781f,
                                         1.22464685e-16f, -0.707106781f, -1.0f, -0.707106781f};

// ---------------- K1: 768->8 1x1 conv + gelu; warp-granular 8-way K-split ----------------
__global__ __launch_bounds__(256) void k1_gemm(const float* __restrict__ fm,
                                               const float* __restrict__ w,
                                               const float* __restrict__ bv,
                                               const float* __restrict__ pdelta){
    extern __shared__ char dsmc[];
    float* wsf = (float*)dsmc;
    ull*   part = (ull*)(dsmc + 24576);
    __shared__ float ridgeS[NP*81];
    for (int i = threadIdx.x; i < NFC*NRC; i += 256){
        int c = i >> 3, r = i & 7;
        wsf[i] = w[r*NFC + c];
    }
    __syncthreads();
    int blk = blockIdx.x;
    int b = blk >> 6, pg = blk & 63;
    int wp = threadIdx.x >> 5, lane = threadIdx.x & 31;
    int p = (pg*32 + lane) << 1;
    const float* x = fm + (size_t)b*NFC*HW + (size_t)(wp*96)*HW + p;
    const float* wc0 = wsf + wp*96*8;
    ull acc[NRC];
    #pragma unroll
    for (int r = 0; r < NRC; r++) acc[r] = 0ull;
    #pragma unroll 8
    for (int c = 0; c < 96; c++){
        ull xv = *(const ull*)(x + (size_t)c*HW);
        const float* wc = wc0 + c*8;
        #pragma unroll
        for (int r = 0; r < NRC; r++){
            float wv = wc[r];
            acc[r] = fma2(pack2(wv, wv), xv, acc[r]);
        }
    }
    ull* pr = part + lane*65 + wp*8;
    #pragma unroll
    for (int r = 0; r < NRC; r++) pr[r] = acc[r];
    __syncthreads();
    int r = threadIdx.x >> 5, pl = threadIdx.x & 31;
    ull s = part[pl*65 + r];
    #pragma unroll
    for (int ww = 1; ww < 8; ww++) s = add2(s, part[pl*65 + ww*8 + r]);
    float lo, hi; unpack2(s, lo, hi);
    float bb = bv[r]; lo += bb; hi += bb;
    float2 v; v.x = geluf(lo); v.y = geluf(hi);
    int po = (pg*32 + pl) << 1;
    *(float2*)(g_cpre + (size_t)b*NRC*HW + (size_t)r*HW + po) = v;

    if (blockIdx.x == 0){
        const float Ls[3] = {0.45f, 0.75f, 1.05f};
        const float Wv[3] = {0.14f, 0.2f, 0.28f};
        for (int i = threadIdx.x; i < NP*81; i += 256){
            int pp = i/81, idx = i%81, ky = idx/9, kx = idx%9;
            float yy = -1.0f + 0.25f*ky, xx = -1.0f + 0.25f*kx;
            float ca = c_ca[pp], sa = c_sa[pp];
            float L = Ls[pp%3], W = Wv[(pp/3)%3];
            float xr = xx*ca + yy*sa;
            float yr = -xx*sa + yy*ca;
            float xl = __fdividef(xr, L);
            float tt = 1.0f - fminf(fabsf(xl), 1.0f);
            float tp = tt*sqrtf(tt);
            float yrw = __fdividef(yr, W);
            float core = __expf(-0.5f*(xl*xl + yrw*yrw));
            ridgeS[i] = tp * core * fmaxf(1.0f - yrw*yrw, 0.0f);
        }
        __syncthreads();
        int wpp = threadIdx.x >> 5, ln = threadIdx.x & 31;
        float* rp = ridgeS + wpp*81;
        float su = 0.f;
        for (int j = ln; j < 81; j += 32) su += rp[j];
        #pragma unroll
        for (int o = 16; o > 0; o >>= 1) su += __shfl_xor_sync(0xffffffffu, su, o);
        float mean = su*(1.0f/81.0f);
        float a = 0.f;
        for (int j = ln; j < 81; j += 32) a += fabsf(rp[j]-mean);
        #pragma unroll
        for (int o = 16; o > 0; o >>= 1) a += __shfl_xor_sync(0xffffffffu, a, o);
        float den = fmaxf(a, 1e-6f);
        for (int j = ln; j < 81; j += 32)
            g_kern[wpp*81+j] = (rp[j]-mean)/den + 0.05f*pdelta[wpp*81+j];
    }
}

// ---------------- K23: conv3x3+gelu on halo-2 region, cm/dn, hp, cs, stats ----------------
__global__ __launch_bounds__(512) void k23_conv(const float* __restrict__ w,
                                                const float* __restrict__ bv){
    __shared__ float ws[576];            // [(ic*9+tap)*8 + oc]
    __shared__ float bs[NRC];
    __shared__ float ts[NRC][22][22];    // cpre, halo 3
    __shared__ float cr[NRC][20][20];    // carrier, halo 2
    __shared__ float cms[20][20];
    __shared__ float hps[18][18];
    __shared__ float red[5][8];
    int tid = threadIdx.x;
    for (int i = tid; i < 576; i += 512) ws[i] = w[(i & 7)*72 + (i >> 3)];
    if (tid < NRC) bs[tid] = bv[tid];
    int blk = blockIdx.x; int b = blk >> 4, tile = blk & 15;
    int ty0 = (tile >> 2) << 4, tx0 = (tile & 3) << 4;
    const float* in = g_cpre + (size_t)b*NRC*HW;
    for (int i = tid; i < NRC*484; i += 512){
        int ic = i / 484, rem = i % 484, ly = rem / 22, lx = rem % 22;
        int gy = ty0 - 3 + ly, gx = tx0 - 3 + lx;
        float v = 0.f;
        if (gy >= 0 && gy < 64 && gx >= 0 && gx < 64) v = in[ic*HW + gy*64 + gx];
        ts[ic][ly][lx] = v;
    }
    __syncthreads();
    // conv on 20x20 (halo 2): 200 pairs x 8 oc
    for (int i = tid; i < 1600; i += 512){
        int oc = i / 200, pi = i % 200;
        int py = pi / 10, px = (pi % 10) << 1;
        float bb = bs[oc];
        ull acc = pack2(bb, bb);
        #pragma unroll
        for (int ic = 0; ic < NRC; ic++){
            #pragma unroll
            for (int dy = 0; dy < 3; dy++){
                #pragma unroll
                for (int dx = 0; dx < 3; dx++){
                    float vlo = ts[ic][py+dy][px+dx];
                    float vhi = ts[ic][py+dy][px+dx+1];
                    float wv = ws[(ic*9 + dy*3 + dx)*8 + oc];
                    acc = fma2(pack2(wv, wv), pack2(vlo, vhi), acc);
                }
            }
        }
        float lo, hi; unpack2(acc, lo, hi);
        cr[oc][py][px]   = geluf(lo);
        cr[oc][py][px+1] = geluf(hi);
    }
    __syncthreads();
    // cm on 20x20 (0 if OOB); dn + g_car for central 16x16
    for (int i = tid; i < 400; i += 512){
        int ly = i / 20, lx = i % 20;
        int gy = ty0 - 2 + ly, gx = tx0 - 2 + lx;
        float cmv = 0.f;
        if (gy >= 0 && gy < 64 && gx >= 0 && gx < 64){
            float m = 0.f;
            #pragma unroll
            for (int oc = 0; oc < NRC; oc++) m += cr[oc][ly][lx];
            cmv = m * 0.125f;
        }
        cms[ly][lx] = cmv;
        if (ly >= 2 && ly < 18 && lx >= 2 && lx < 18){
            float a = 0.f;
            #pragma unroll
            for (int oc = 0; oc < NRC; oc++) a += fabsf(cr[oc][ly][lx]);
            g_dn[b*HW + gy*64 + gx] = a * 0.125f;
        }
    }
    // g_car central, float2 stores
    for (int i = tid; i < 1024; i += 512){
        int oc = i >> 7, pi = i & 127;
        int py = pi >> 3, px = (pi & 7) << 1;
        float2 v; v.x = cr[oc][py+2][px+2]; v.y = cr[oc][py+2][px+3];
        *(float2*)(g_car + (size_t)b*NRC*HW + (size_t)oc*HW + (ty0+py)*64 + tx0+px) = v;
    }
    __syncthreads();
    // hp on 18x18 (halo 1)
    for (int i = tid; i < 324; i += 512){
        int ly = i/18, lx = i%18;
        int gy = ty0-1+ly, gx = tx0-1+lx;
        float v = 0.f;
        if (gy>=0 && gy<64 && gx>=0 && gx<64){
            float s = 0.f;
            #pragma unroll
            for (int dy = 0; dy < 3; dy++)
                #pragma unroll
                for (int dx = 0; dx < 3; dx++) s += cms[ly+dy][lx+dx];
            v = cms[ly+1][lx+1] - s*(1.0f/9.0f);
        }
        hps[ly][lx] = v;
    }
    __syncthreads();
    // cs + stats (central 16x16, tid<256)
    if (tid < 256){
        int ty = tid >> 4, tx = tid & 15;
        float s = 0.f;
        #pragma unroll
        for (int dy = 0; dy < 3; dy++)
            #pragma unroll
            for (int dx = 0; dx < 3; dx++) s += fabsf(hps[ty+dy][tx+dx]);
        float cs = s*(1.0f/9.0f);
        int gi = b*HW + (ty0+ty)*64 + (tx0+tx);
        g_hp[gi] = hps[ty+1][tx+1];
        g_cs[gi] = cs;
        float a = 0.f;
        #pragma unroll
        for (int oc = 0; oc < NRC; oc++) a += fabsf(cr[oc][ty+2][tx+2]);
        float d = a * 0.125f;
        float cmn = cs, cmx = cs, dmn = d, dmx = d, ds = d;
        #pragma unroll
        for (int o = 16; o > 0; o >>= 1){
            cmn = fminf(cmn, __shfl_xor_sync(0xffffffffu, cmn, o));
            cmx = fmaxf(cmx, __shfl_xor_sync(0xffffffffu, cmx, o));
            dmn = fminf(dmn, __shfl_xor_sync(0xffffffffu, dmn, o));
            dmx = fmaxf(dmx, __shfl_xor_sync(0xffffffffu, dmx, o));
            ds += __shfl_xor_sync(0xffffffffu, ds, o);
        }
        int wd = tid >> 5, lane = tid & 31;
        if (lane == 0){ red[0][wd]=cmn; red[1][wd]=cmx; red[2][wd]=dmn; red[3][wd]=dmx; red[4][wd]=ds; }
    }
    __syncthreads();
    if (tid == 0){
        float c0=red[0][0], c1=red[1][0], d0=red[2][0], d1=red[3][0], dsu=red[4][0];
        for (int j = 1; j < 8; j++){
            c0 = fminf(c0, red[0][j]); c1 = fmaxf(c1, red[1][j]);
            d0 = fminf(d0, red[2][j]); d1 = fmaxf(d1, red[3][j]);
            dsu += red[4][j];
        }
        float* pp = g_part + blk*8;
        pp[0]=c0; pp[1]=c1; pp[2]=d0; pp[3]=d1; pp[4]=dsu;
    }
}

// ---------------- K57: stats + gating + responses + final ss; 256 blocks of 16x8 ----------------
__global__ __launch_bounds__(256) void k57_main(const float* __restrict__ theta,
                                                const float* __restrict__ length,
                                                const float* __restrict__ width,
                                                const float* __restrict__ plog,
                                                const float* __restrict__ obj,
                                                const float* __restrict__ alpha,
                                                const float* __restrict__ curv){
    __shared__ float hps[18*26];
    __shared__ float kern[NP*81];
    __shared__ float m0s[20*28];
    __shared__ float g0s[12*20];
    __shared__ float ers[16*24];
    __shared__ float s0s[10*18];
    __shared__ float obs[10*18];
    __shared__ float cmin[16*28];
    __shared__ float cmax[8*24];
    __shared__ float gcol[8*20];
    __shared__ float st_s[5];
    int blk = blockIdx.x; int b = blk >> 5, tile = blk & 31;
    int ty0 = (tile >> 2) << 3, tx0 = (tile & 3) << 4;
    int tid = threadIdx.x;

    const float* hp = g_hp + b*HW;
    for (int i = tid; i < 468; i += 256){
        int ly = i/26, lx = i%26;
        int gy = ty0-5+ly, gx = tx0-5+lx;
        hps[i] = (gy>=0 && gy<64 && gx>=0 && gx<64) ? hp[gy*64+gx] : 0.f;
    }
    for (int i = tid; i < NP*81; i += 256) kern[i] = g_kern[i];
    if (tid < 32){
        int lane = tid;
        float v0=1e30f, v1=-1e30f, v2=1e30f, v3=-1e30f, v4=0.f;
        if (lane < 16){
            const float* pp = g_part + (b*16+lane)*8;
            v0=pp[0]; v1=pp[1]; v2=pp[2]; v3=pp[3]; v4=pp[4];
        }
        #pragma unroll
        for (int o = 8; o > 0; o >>= 1){
            v0 = fminf(v0, __shfl_down_sync(0xffffffffu, v0, o));
            v1 = fmaxf(v1, __shfl_down_sync(0xffffffffu, v1, o));
            v2 = fminf(v2, __shfl_down_sync(0xffffffffu, v2, o));
            v3 = fmaxf(v3, __shfl_down_sync(0xffffffffu, v3, o));
            v4 +=           __shfl_down_sync(0xffffffffu, v4, o);
        }
        if (lane == 0){
            st_s[0]=v0; st_s[1]=v1; st_s[2]=v2; st_s[3]=v3; st_s[4]=v4*(1.0f/4096.0f);
        }
    }
    __syncthreads();

    float csmn = st_s[0], csmx = st_s[1], dmn = st_s[2], dmx = st_s[3];
    float m = fmaxf(st_s[4], 1e-6f);
    float csden = fmaxf(csmx - csmn, 1e-6f);
    float ddmn = dmn/m, ddmx = dmx/m;
    float dsden = fmaxf(ddmx - ddmn, 1e-6f);
    const float* csb = g_cs + b*HW; const float* dnb = g_dn + b*HW;
    for (int i = tid; i < 560; i += 256){
        int ly = i/28, lx = i%28;
        int gy = ty0-6+ly, gx = tx0-6+lx;
        float mv = 1.0f, gv = 0.0f;
        if (gy>=0 && gy<64 && gx>=0 && gx<64){
            int gi = gy*64+gx;
            float csn = (csb[gi]-csmn)/csden;
            float dsn = (dnb[gi]/m - ddmn)/dsden;
            float ev = 0.65f*csn + 0.35f*dsn;
            mv = (ev >= 0.2f) ? 1.0f : 0.0f;
            gv = sigmf_((ev - 0.2f)*12.5f);
        }
        m0s[i] = mv;
        if (ly >= 4 && ly < 16 && lx >= 4 && lx < 24)
            g0s[(ly-4)*20 + (lx-4)] = gv;
    }
    __syncthreads();
    // column min5 of m0s (16 rows x 28 cols)
    for (int i = tid; i < 448; i += 256){
        int ly = i/28, lx = i%28;
        float e = m0s[ly*28+lx];
        #pragma unroll
        for (int dy = 1; dy < 5; dy++) e = fminf(e, m0s[(ly+dy)*28+lx]);
        cmin[i] = e;
    }
    __syncthreads();
    // er (16x24) + s0/obs (10x18)
    for (int i = tid; i < 384; i += 256){
        int ly = i/24, lx = i%24;
        int gy = ty0-4+ly, gx = tx0-4+lx;
        float e = 0.f;
        if (gy>=0 && gy<64 && gx>=0 && gx<64){
            e = cmin[ly*28+lx];
            #pragma unroll
            for (int dx = 1; dx < 5; dx++) e = fminf(e, cmin[ly*28+lx+dx]);
        }
        ers[i] = e;
    }
    const float* ob = obj + b*HW;
    const float Ls[3] = {0.45f, 0.75f, 1.05f};
    const float Wv[3] = {0.14f, 0.2f, 0.28f};
    for (int i = tid; i < 180; i += 256){
        int ly = i/18, lx = i%18;
        int gy = ty0-1+ly, gx = tx0-1+lx;
        float sv = 0.f, ov = 0.f;
        if (gy>=0 && gy<64 && gx>=0 && gx<64){
            int gi = gy*64+gx; int t = b*HW + gi;
            ov = sigmf_(ob[gi]);
            float bias[NP];
            float ta = tanhf(theta[t]) * 3.14159265358979323846f;
            float cta, sta; __sincosf(ta, &sta, &cta);
            float lv = sigmf_(length[t])*0.85f + 0.25f;
            float wv = sigmf_(width[t])*0.22f + 0.08f;
            #pragma unroll
            for (int p = 0; p < NP; p++){
                float la = Ls[p%3], wa = Wv[(p/3)%3];
                float dl = lv - la, dw = wv - wa;
                bias[p] = plog[(size_t)b*NP*HW + p*HW + gi]
                        + 1.25f*(cta*c_ca[p] + sta*c_sa[p])
                        - dl*dl*12.5f
                        - dw*dw*100.0f;
            }
            int i1 = 0; float m1 = bias[0];
            #pragma unroll
            for (int p = 1; p < NP; p++) if (bias[p] > m1){ m1 = bias[p]; i1 = p; }
            int i2 = (i1 == 0) ? 1 : 0; float m2 = -1e30f;
            #pragma unroll
            for (int p = 0; p < NP; p++) if (p != i1 && bias[p] > m2){ m2 = bias[p]; i2 = p; }
            float e2 = __expf(m2 - m1);
            float inv = 1.0f/(1.0f + e2);
            float pw1 = inv, pw2 = e2*inv;
            const float* k1p = kern + i1*81;
            const float* k2p = kern + i2*81;
            float r1 = 0.f, r2v = 0.f;
            #pragma unroll
            for (int ky = 0; ky < 9; ky++){
                #pragma unroll
                for (int kx = 0; kx < 9; kx++){
                    float v = hps[(ly+ky)*26 + (lx+kx)];
                    r1  = fmaf(k1p[ky*9+kx], v, r1);
                    r2v = fmaf(k2p[ky*9+kx], v, r2v);
                }
            }
            sv = pw1*r1 + pw2*r2v;
        }
        s0s[i] = sv;
        obs[i] = ov;
    }
    __syncthreads();
    // column passes: cmax (max9 over ers rows, 8x24), gcol (max5 over g0s rows, 8x20)
    for (int i = tid; i < 352; i += 256){
        if (i < 192){
            int ty = i/24, lx = i%24;
            float e = ers[ty*24+lx];
            #pragma unroll
            for (int dy = 1; dy < 9; dy++) e = fmaxf(e, ers[(ty+dy)*24+lx]);
            cmax[i] = e;
        } else {
            int j = i - 192;
            int ty = j/20, lx = j%20;
            float g = g0s[ty*20+lx];
            #pragma unroll
            for (int dy = 1; dy < 5; dy++) g = fmaxf(g, g0s[(ty+dy)*20+lx]);
            gcol[j] = g;
        }
    }
    __syncthreads();
    if (tid < 128){
        int ty = tid >> 4, tx = tid & 15;
        float mask = cmax[ty*24+tx];
        #pragma unroll
        for (int dx = 1; dx < 9; dx++) mask = fmaxf(mask, cmax[ty*24+tx+dx]);
        float gate = gcol[ty*20+tx];
        #pragma unroll
        for (int dx = 1; dx < 5; dx++) gate = fmaxf(gate, gcol[ty*20+tx+dx]);
        float blob = 0.f, ssum = 0.f;
        #pragma unroll
        for (int dy = 0; dy < 3; dy++)
            #pragma unroll
            for (int dx = 0; dx < 3; dx++){
                blob += obs[(ty+dy)*18 + (tx+dx)];
                ssum += s0s[(ty+dy)*18 + (tx+dx)];
            }
        blob *= (1.0f/9.0f);
        float ss1 = s0s[(ty+1)*18 + (tx+1)] - ssum*(1.0f/9.0f);
        int t = b*HW + (ty0+ty)*64 + (tx0+tx);
        float gatef = gate * mask;
        float dmean = fmaxf(st_s[4], 1e-6f);
        float dens = g_dn[t] / dmean;
        float sg = sigmf_(alpha[t]) * (blob * gatef) * (0.7f + 0.3f*fminf(fmaxf(dens, 0.f), 2.f));
        g_sf[t] = sg * ss1 * (1.0f + 0.15f*tanhf(curv[t]));
    }
}

// ---------------- K8: feats -> 8 (gelu) -> 768; warp-granular 8-way fc-split ----------------
__global__ __launch_bounds__(256) void k8_out(const float* __restrict__ theta,
                                              const float* __restrict__ curv,
                                              const float* __restrict__ w1,
                                              const float* __restrict__ b1,
                                              const float* __restrict__ w2,
                                              const float* __restrict__ b2,
                                              float* __restrict__ out){
    extern __shared__ ull sh[];
    ull*   w2p = sh;
    float* b2s = (float*)(sh + NFC*NRC);
    ull*   w1p = (ull*)(b2s + NFC);
    float* b1s = (float*)(w1p + 96);
    for (int i = threadIdx.x; i < NFC*NRC; i += 256){ float v = w2[i]; w2p[i] = pack2(v, v); }
    for (int i = threadIdx.x; i < NFC; i += 256) b2s[i] = b2[i];
    for (int i = threadIdx.x; i < 96; i += 256){ float v = w1[i]; w1p[i] = pack2(v, v); }
    if (threadIdx.x < 8) b1s[threadIdx.x] = b1[threadIdx.x];
    __syncthreads();

    int blk = blockIdx.x;
    int b = blk >> 6, pg = blk & 63;
    int wp = threadIdx.x >> 5, lane = threadIdx.x & 31;
    int p = (pg*32 + lane) << 1;
    int base = b*HW + p;
    float2 ss = *(const float2*)(g_sf + base);
    float2 th = *(const float2*)(theta + base);
    float2 cv = *(const float2*)(curv + base);
    ull f[12];
    const float* car = g_car + (size_t)b*NRC*HW + p;
    #pragma unroll
    for (int r = 0; r < NRC; r++){
        float2 c = *(const float2*)(car + (size_t)r*HW);
        f[r] = pack2(c.x*ss.x, c.y*ss.y);
    }
    f[8] = pack2(ss.x, ss.y);
    const float PIF = 3.14159265358979323846f;
    float a0 = tanhf(th.x)*PIF, a1 = tanhf(th.y)*PIF;
    f[9]  = pack2(cosf(a0)*ss.x, cosf(a1)*ss.y);
    f[10] = pack2(sinf(a0)*ss.x, sinf(a1)*ss.y);
    f[11] = pack2(tanhf(cv.x)*ss.x, tanhf(cv.y)*ss.y);

    ull h[NRC];
    #pragma unroll
    for (int r = 0; r < NRC; r++){
        ull acc = pack2(b1s[r], b1s[r]);
        #pragma unroll
        for (int j = 0; j < 12; j++) acc = fma2(w1p[r*12+j], f[j], acc);
        float lo, hi; unpack2(acc, lo, hi);
        h[r] = pack2(geluf(lo), geluf(hi));
    }
    float* o = out + (size_t)b*NFC*HW + p;
    int fc0 = wp * 96;
    #pragma unroll 4
    for (int j = 0; j < 96; j++){
        int fc = fc0 + j;
        float bb = b2s[fc];
        ull acc = pack2(bb, bb);
        const ull* wr = w2p + fc*8;
        #pragma unroll
        for (int r = 0; r < NRC; r++) acc = fma2(wr[r], h[r], acc);
        float2 v; unpack2(acc, v.x, v.y);
        *(float2*)(o + (size_t)fc*HW) = v;
    }
}

// ---------------- host ----------------
extern "C" void kernel_launch(void* const* d_in, const int* in_sizes, int n_in,
                              void* d_out, int out_size){
    const float* fm    = (const float*)d_in[0];
    const float* theta = (const float*)d_in[1];
    const float* len   = (const float*)d_in[2];
    const float* wid   = (const float*)d_in[3];
    const float* curv  = (const float*)d_in[4];
    const float* alpha = (const float*)d_in[5];
    const float* obj   = (const float*)d_in[6];
    const float* plog  = (const float*)d_in[7];
    const float* fp1w  = (const float*)d_in[8];
    const float* fp1b  = (const float*)d_in[9];
    const float* fp2w  = (const float*)d_in[10];
    const float* fp2b  = (const float*)d_in[11];
    const float* pm1w  = (const float*)d_in[12];
    const float* pm1b  = (const float*)d_in[13];
    const float* pm2w  = (const float*)d_in[14];
    const float* pm2b  = (const float*)d_in[15];
    const float* pdel  = (const float*)d_in[16];

    cudaFuncSetAttribute(k1_gemm, cudaFuncAttributeMaxDynamicSharedMemorySize, 41216);
    cudaFuncSetAttribute(k8_out,  cudaFuncAttributeMaxDynamicSharedMemorySize, 53056);

    k1_gemm<<<512,256,41216>>>(fm, fp1w, fp1b, pdel);
    k23_conv<<<128,512>>>(fp2w, fp2b);
    k57_main<<<256,256>>>(theta, len, wid, plog, obj, alpha, curv);
    k8_out<<<512,256,53056>>>(theta, curv, pm1w, pm1b, pm2w, pm2b, (float*)d_out);
}